// round 12
// baseline (speedup 1.0000x reference)
#include <cuda_runtime.h>
#include <cuda_fp16.h>
#include <cuda_fp8.h>
#include <cstdint>
#include <math.h>

#define Bn 8
#define Cn 256
#define Ln 512
#define NPn 6
#define KMAXn 17
#define HIDn 1024
#define SUMK 72

typedef long long ll;
typedef __half hf;
typedef unsigned char u8;

// ---------------- scratch (device globals) ----------------------------------
__device__ __align__(16) hf g_ag  [(size_t)Bn*NPn*Cn*Ln];
__device__ __align__(16) hf g_vv  [(size_t)Bn*NPn*Cn*Ln];
__device__ __align__(16) hf g_v   [(size_t)Bn*NPn*Cn*Ln];
__device__ __align__(16) hf g_dcn [(size_t)Bn*NPn*Cn*Ln];
__device__ __align__(16) hf g_prod[(size_t)Bn*NPn*Cn*Ln];
__device__ __align__(16) u8 g_off [(size_t)Bn*Cn*Ln*SUMK];
__device__ __align__(16) u8 g_ml  [(size_t)Bn*Cn*Ln*SUMK];
__device__ __align__(16) float g_y [(size_t)Bn*Cn*Ln];
__device__ __align__(16) hf g_tn  [(size_t)Bn*Cn*Ln];
__device__ __align__(16) hf g_h   [(size_t)Bn*HIDn*Ln];
__device__ float g_bps[Cn];
__device__ __align__(16) hf g_wa  [NPn*Cn*Cn];
__device__ __align__(16) hf g_wvd [NPn*Cn*Cn];
__device__ __align__(16) hf g_wod [NPn*Cn*Cn];
__device__ __align__(16) hf g_wv  [NPn*Cn*Cn];
__device__ __align__(16) hf g_wp  [NPn*Cn*Cn];
__device__ __align__(16) hf g_woff[(size_t)NPn*KMAXn*Cn*Cn];
__device__ __align__(16) hf g_wm  [(size_t)NPn*KMAXn*Cn*Cn];
__device__ __align__(16) hf g_w1  [HIDn*Cn];
__device__ __align__(16) hf g_w2  [Cn*HIDn];
__device__ __align__(16) hf g_xb  [(size_t)Bn*Cn*Ln];

__device__ __forceinline__ float gelu_f(float v) {
    return 0.5f * v * (1.0f + erff(v * 0.7071067811865476f));
}
__device__ __forceinline__ float fp8f(u8 v) {
    __half_raw h = __nv_cvt_fp8_to_halfraw(v, __NV_E4M3);
    return __half2float(*(__half*)&h);
}

// ---------------- fused conversion --------------------------------------
struct CvtArgs {
    const float* src[10];
    hf* dst[10];
    int cum[11];
};
__global__ void __launch_bounds__(256)
cvtall_k(CvtArgs a)
{
    int total = a.cum[10];
    for (int i = blockIdx.x * 256 + threadIdx.x; i < total; i += gridDim.x * 256) {
        int s = 0;
        #pragma unroll
        for (int j = 1; j < 10; j++) if (i >= a.cum[j]) s = j;
        int off = i - a.cum[s];
        a.dst[s][off] = __float2half(a.src[s][off]);
    }
}

__global__ void bpsum_k(const float* __restrict__ bp, float* __restrict__ out)
{
    int c = threadIdx.x;
    float s = 0.f;
    #pragma unroll
    for (int i = 0; i < NPn; i++) s += bp[i * Cn + c];
    out[c] = s;
}

// ---------------- asm wrappers ----------------------------------------------
__device__ __forceinline__ void cpa16u(uint32_t dst, const void* src) {
    asm volatile("cp.async.cg.shared.global [%0], [%1], 16;\n" :: "r"(dst), "l"(src));
}
__device__ __forceinline__ void ldsm4(uint32_t addr, uint32_t& r0, uint32_t& r1,
                                      uint32_t& r2, uint32_t& r3) {
    asm volatile("ldmatrix.sync.aligned.m8n8.x4.shared.b16 {%0,%1,%2,%3}, [%4];\n"
        : "=r"(r0), "=r"(r1), "=r"(r2), "=r"(r3) : "r"(addr));
}
__device__ __forceinline__ void ldsm4t(uint32_t addr, uint32_t& r0, uint32_t& r1,
                                       uint32_t& r2, uint32_t& r3) {
    asm volatile("ldmatrix.sync.aligned.m8n8.x4.trans.shared.b16 {%0,%1,%2,%3}, [%4];\n"
        : "=r"(r0), "=r"(r1), "=r"(r2), "=r"(r3) : "r"(addr));
}
__device__ __forceinline__ void mma_h32(float& d0, float& d1, float& d2, float& d3,
                                        uint32_t a0, uint32_t a1, uint32_t a2, uint32_t a3,
                                        uint32_t b0, uint32_t b1) {
    asm volatile(
        "mma.sync.aligned.m16n8k16.row.col.f32.f16.f16.f32 "
        "{%0,%1,%2,%3},{%4,%5,%6,%7},{%8,%9},{%0,%1,%2,%3};\n"
        : "+f"(d0), "+f"(d1), "+f"(d2), "+f"(d3)
        : "r"(a0), "r"(a1), "r"(a2), "r"(a3), "r"(b0), "r"(b1));
}
__device__ __forceinline__ void mma_h16(uint32_t& d0, uint32_t& d1,
                                        uint32_t a0, uint32_t a1, uint32_t a2, uint32_t a3,
                                        uint32_t b0, uint32_t b1) {
    asm volatile(
        "mma.sync.aligned.m16n8k16.row.col.f16.f16.f16.f16 "
        "{%0,%1},{%2,%3,%4,%5},{%6,%7},{%0,%1};\n"
        : "+r"(d0), "+r"(d1)
        : "r"(a0), "r"(a1), "r"(a2), "r"(a3), "r"(b0), "r"(b1));
}
__device__ __forceinline__ unsigned short cvt_e4m3x2(float r0, float r1) {
    unsigned short u;
    asm("cvt.rn.satfinite.e4m3x2.f32 %0, %1, %2;" : "=h"(u) : "f"(r1), "f"(r0));
    return u;   // low byte = r0, high = r1
}

// ---------------- GEMM core (128x128 CTA, 8 warps, warp tile 32x64) ----------
// OutT: hf -> fp16 out; float -> fp32 out; u8 -> e4m3 out with x16 scale.
template<int EPI, bool STACK, bool ACC16, typename OutT>
__device__ __forceinline__ void gemm_core(
    hf (*As)[128][32], hf (*Bs)[4096],
    const hf* __restrict__ Wz, const float* __restrict__ bz,
    const hf* __restrict__ Xz, OutT* __restrict__ Yz,
    int KDIM, int m0, int n0,
    const void* __restrict__ aux, const float* __restrict__ svec)
{
    const int tid = threadIdx.x, lane = tid & 31, wid = tid >> 5;
    const int wm = wid >> 1, wn = wid & 1;

    float acc[ACC16 ? 1 : 2][8][4];
    uint32_t acch[ACC16 ? 2 : 1][8][2];
    if (!ACC16) {
        #pragma unroll
        for (int i = 0; i < (ACC16 ? 1 : 2); i++)
            #pragma unroll
            for (int j = 0; j < 8; j++)
                #pragma unroll
                for (int q = 0; q < 4; q++) acc[i][j][q] = 0.f;
    } else {
        #pragma unroll
        for (int i = 0; i < (ACC16 ? 2 : 1); i++)
            #pragma unroll
            for (int j = 0; j < 8; j++) { acch[i][j][0] = 0u; acch[i][j][1] = 0u; }
    }

    const uint32_t asBase = (uint32_t)__cvta_generic_to_shared(&As[0][0][0]);
    const uint32_t bBase  = (uint32_t)__cvta_generic_to_shared(&Bs[0][0]);

    const int mA = tid >> 2, cA = tid & 3;
    const int kB = tid >> 4, nB = tid & 15;
    const hf *srcA0, *srcA1;
    if (STACK) {
        srcA0 = Wz + (ll)(m0 + mA) * Cn + cA * 8;
        srcA1 = Wz + (ll)(m0 + mA + 64) * Cn + cA * 8;
    } else {
        srcA0 = Wz + (ll)(m0 + mA) * KDIM + cA * 8;
        srcA1 = Wz + (ll)(m0 + mA + 64) * KDIM + cA * 8;
    }
    const hf* srcB0 = Xz + (ll)kB * Ln + n0 + nB * 8;
    const hf* srcB1 = Xz + (ll)(kB + 16) * Ln + n0 + nB * 8;
    const uint32_t dA0 = asBase + (uint32_t)(mA * 64 + (cA ^ ((mA >> 1) & 3)) * 16);
    const uint32_t dA1 = asBase + (uint32_t)((mA + 64) * 64 + (cA ^ (((mA + 64) >> 1) & 3)) * 16);
    const uint32_t dB0 = bBase + (uint32_t)((kB * 16 + (nB ^ (kB & 7))) * 16);
    const uint32_t dB1 = bBase + (uint32_t)(((kB + 16) * 16 + (nB ^ ((kB + 16) & 7))) * 16);
    int kctr = 0;

    auto loadStage = [&](uint32_t so) {
        cpa16u(dA0 + so, srcA0);
        cpa16u(dA1 + so, srcA1);
        cpa16u(dB0 + so, srcB0);
        cpa16u(dB1 + so, srcB1);
        srcB0 += 32 * Ln; srcB1 += 32 * Ln;
        if (STACK) {
            kctr += 32;
            ll d = 32;
            if ((kctr & 255) == 0) d += (ll)Cn * Cn - 256;
            srcA0 += d; srcA1 += d;
        } else {
            srcA0 += 32; srcA1 += 32;
        }
    };

    uint32_t aAddr[2][2], bAddr[4];
    #pragma unroll
    for (int mt = 0; mt < 2; mt++)
        #pragma unroll
        for (int ks = 0; ks < 2; ks++) {
            int rowp = wm * 32 + mt * 16 + (lane & 15);
            int physA = ((ks * 2) + (lane >> 4)) ^ ((rowp >> 1) & 3);
            aAddr[mt][ks] = asBase + (uint32_t)(rowp * 64 + physA * 16);
        }
    #pragma unroll
    for (int pr = 0; pr < 4; pr++) {
        int phys = (wn * 8 + pr * 2 + (lane >> 4)) ^ (lane & 7);
        bAddr[pr] = bBase + (uint32_t)((lane & 15) * 256 + phys * 16);
    }

    const int nIt = KDIM >> 5;
    loadStage(0);
    asm volatile("cp.async.commit_group;\n");
    loadStage(8192);
    asm volatile("cp.async.commit_group;\n");

    uint32_t ldSlot = 16384, sOff = 0;
    for (int it = 0; it < nIt; it++) {
        if (it + 1 < nIt) asm volatile("cp.async.wait_group 1;\n");
        else              asm volatile("cp.async.wait_group 0;\n");
        __syncthreads();
        if (it + 2 < nIt) {
            loadStage(ldSlot);
            ldSlot = (ldSlot == 16384) ? 0 : ldSlot + 8192;
        }
        asm volatile("cp.async.commit_group;\n");

        #pragma unroll
        for (int ks = 0; ks < 2; ks++) {
            uint32_t fa[2][4];
            {
                uint32_t t0, t1, t2, t3;
                ldsm4(aAddr[0][ks] + sOff, t0, t1, t2, t3);
                fa[0][0] = t0; fa[0][1] = t1; fa[0][2] = t2; fa[0][3] = t3;
                ldsm4(aAddr[1][ks] + sOff, t0, t1, t2, t3);
                fa[1][0] = t0; fa[1][1] = t1; fa[1][2] = t2; fa[1][3] = t3;
            }
            uint32_t fb[4][4];
            #pragma unroll
            for (int pr = 0; pr < 4; pr++) {
                uint32_t t0, t1, t2, t3;
                ldsm4t(bAddr[pr] + (uint32_t)(ks * 4096) + sOff, t0, t1, t2, t3);
                fb[pr][0] = t0; fb[pr][1] = t1; fb[pr][2] = t2; fb[pr][3] = t3;
            }
            #pragma unroll
            for (int mt = 0; mt < 2; mt++)
                #pragma unroll
                for (int nt = 0; nt < 8; nt++) {
                    if (ACC16) {
                        uint32_t c0 = acch[mt][nt][0], c1 = acch[mt][nt][1];
                        mma_h16(c0, c1,
                                fa[mt][0], fa[mt][1], fa[mt][2], fa[mt][3],
                                fb[nt >> 1][(nt & 1) * 2], fb[nt >> 1][(nt & 1) * 2 + 1]);
                        acch[mt][nt][0] = c0; acch[mt][nt][1] = c1;
                    } else {
                        float c0 = acc[mt][nt][0], c1 = acc[mt][nt][1];
                        float c2 = acc[mt][nt][2], c3 = acc[mt][nt][3];
                        mma_h32(c0, c1, c2, c3,
                                fa[mt][0], fa[mt][1], fa[mt][2], fa[mt][3],
                                fb[nt >> 1][(nt & 1) * 2], fb[nt >> 1][(nt & 1) * 2 + 1]);
                        acc[mt][nt][0] = c0; acc[mt][nt][1] = c1;
                        acc[mt][nt][2] = c2; acc[mt][nt][3] = c3;
                    }
                }
        }
        sOff = (sOff == 16384) ? 0 : sOff + 8192;
    }

    // epilogue
    const int row = lane >> 2, colp = (lane & 3) * 2;
    #pragma unroll
    for (int mt = 0; mt < 2; mt++) {
        #pragma unroll
        for (int h = 0; h < 2; h++) {
            int o = m0 + wm * 32 + mt * 16 + row + h * 8;
            float bb = bz[o];
            float sv = (EPI == 3) ? svec[o] : 0.f;
            #pragma unroll
            for (int nt = 0; nt < 8; nt++) {
                int l = n0 + wn * 64 + nt * 8 + colp;
                ll yi = (ll)o * Ln + l;
                float r0, r1;
                if (ACC16) {
                    __half2 hv = *(__half2*)&acch[mt][nt][h];
                    r0 = __low2float(hv) + bb;
                    r1 = __high2float(hv) + bb;
                } else {
                    r0 = acc[mt][nt][h * 2 + 0] + bb;
                    r1 = acc[mt][nt][h * 2 + 1] + bb;
                }
                if (EPI == 1) { r0 = gelu_f(r0); r1 = gelu_f(r1); }
                if (EPI == 2) {
                    __half2 av = *(const __half2*)(((const hf*)aux) + yi);
                    r0 *= __low2float(av); r1 *= __high2float(av);
                }
                if (EPI == 3) {
                    float2 av = *(const float2*)(((const float*)aux) + yi);
                    r0 = av.x + sv * r0; r1 = av.y + sv * r1;
                }
                if (sizeof(OutT) == 1) {
                    // fp8 e4m3 store with x16 scale
                    *(unsigned short*)((u8*)Yz + yi) = cvt_e4m3x2(r0 * 16.0f, r1 * 16.0f);
                } else if (sizeof(OutT) == 2) {
                    __half2 pv = __floats2half2_rn(r0, r1);
                    *(__half2*)((hf*)Yz + yi) = pv;
                } else {
                    float2 fv; fv.x = r0; fv.y = r1;
                    *(float2*)((float*)Yz + yi) = fv;
                }
            }
        }
    }
}

// ---------------- generic GEMM kernel wrapper --------------------------------
template<int EPI, bool STACK, bool ACC16, typename OutT>
__global__ void __launch_bounds__(256, 2)
gemm_t(const hf* __restrict__ W, const float* __restrict__ bias,
       const hf* __restrict__ X, OutT* __restrict__ Y,
       int KDIM, int zB,
       ll wStrideI, int bStrideI,
       ll xStrideB, ll xStrideI,
       ll yStrideB, ll yStrideI,
       const void* __restrict__ aux, ll aStrideB, ll aStrideI,
       const float* __restrict__ svec)
{
    __shared__ __align__(16) hf As[3][128][32];
    __shared__ __align__(16) hf Bs[3][4096];
    const int z = blockIdx.z;
    const int b = z % zB, br = z / zB;
    const hf*  Wz = W + (ll)br * wStrideI;
    const float* bz = bias + (ll)br * bStrideI;
    const hf*  Xz = X + (ll)b * xStrideB + (ll)br * xStrideI;
    OutT* Yz = Y + (ll)b * yStrideB + (ll)br * yStrideI;
    const void* auxp = nullptr;
    if (EPI == 2) auxp = ((const hf*)aux) + (ll)b * aStrideB + (ll)br * aStrideI;
    if (EPI == 3) auxp = ((const float*)aux) + (ll)b * aStrideB + (ll)br * aStrideI;
    gemm_core<EPI, STACK, ACC16, OutT>(As, Bs, Wz, bz, Xz, Yz, KDIM,
                                       blockIdx.y * 128, blockIdx.x * 128, auxp, svec);
}

// ---------------- merged G1+G2 kernel -----------------------------------------
__global__ void __launch_bounds__(256, 2)
g12_k(const hf* __restrict__ wa, const float* __restrict__ ba,
      const hf* __restrict__ wv, const float* __restrict__ bv,
      const hf* __restrict__ xb, hf* __restrict__ ag, hf* __restrict__ vvp)
{
    __shared__ __align__(16) hf As[3][128][32];
    __shared__ __align__(16) hf Bs[3][4096];
    int t = blockIdx.y;
    int b = blockIdx.z;
    const ll SB = (ll)NPn * Cn * Ln;
    const hf* Xz = xb + (ll)b * Cn * Ln;
    if (t < 12) {
        gemm_core<1, false, true, hf>(As, Bs, wa, ba, Xz, ag + (ll)b * SB, Cn,
                                      t * 128, blockIdx.x * 128, nullptr, nullptr);
    } else {
        gemm_core<0, false, true, hf>(As, Bs, wv, bv, Xz, vvp + (ll)b * SB, Cn,
                                      (t - 12) * 128, blockIdx.x * 128, nullptr, nullptr);
    }
}

// ---------------- fused off+ml mega-GEMM (fp8 out) ---------------------------
__global__ void __launch_bounds__(256, 2)
offml_k(const hf* __restrict__ woff, const hf* __restrict__ wm,
        const float* __restrict__ boff, const float* __restrict__ bm,
        const hf* __restrict__ ag, u8* __restrict__ offp, u8* __restrict__ mlp)
{
    __shared__ __align__(16) hf As[3][128][32];
    __shared__ __align__(16) hf Bs[3][4096];
    const int bnd[7]  = {0, 14, 32, 54, 80, 110, 144};
    const int preK[6] = {0, 7, 16, 27, 40, 55};
    int t = blockIdx.y;
    int b = blockIdx.z;
    int kind = (t >= 144) ? 1 : 0;
    int tt = t - kind * 144;
    int br = 0;
    #pragma unroll
    for (int j = 1; j < 6; j++) if (tt >= bnd[j]) br = j;
    int mloc = (tt - bnd[br]) * 128;
    int K = 7 + 2 * br;
    const hf*    W  = (kind ? wm : woff) + (ll)br * KMAXn * Cn * Cn + (ll)mloc * Cn;
    const float* bz = (kind ? bm : boff) + br * KMAXn * Cn + mloc;
    const hf*    Xz = ag + ((ll)b * NPn + br) * ((ll)Cn * Ln);
    u8* Y = (kind ? mlp : offp) + (ll)preK[br] * ((ll)Bn * Cn * Ln)
            + (ll)b * Cn * K * Ln + (ll)mloc * Ln;
    gemm_core<0, false, true, u8>(As, Bs, W, bz, Xz, Y, Cn, 0, blockIdx.x * 128,
                                  nullptr, nullptr);
}

// ---------------- DCN (fp8 off/ml in, fp16 out) -------------------------------
template<int K>
__device__ __forceinline__ void dcn_body(
    const u8* __restrict__ off_all, const u8* __restrict__ ml_all,
    const hf* __restrict__ v_all, hf* __restrict__ dcn,
    int branch, ll regionBase)
{
    ll idx = (ll)blockIdx.x * 256 + threadIdx.x;
    int l = (int)(idx & (Ln - 1));
    int c = (int)((idx >> 9) & (Cn - 1));
    int b = (int)(idx >> 17);
    ll rowBase = regionBase + ((ll)b * Cn * K + (ll)c * K) * Ln + l;
    const u8* op = off_all + rowBase;
    const u8* mp = ml_all + rowBase;
    const hf* vp = v_all + ((ll)b * NPn + branch) * ((ll)Cn * Ln) + (ll)c * Ln;

    float mlv[K];
    float mx = -3.4e38f;
    #pragma unroll
    for (int k = 0; k < K; k++) {
        mlv[k] = fp8f(mp[(ll)k * Ln]) * 0.0625f;   // unscale BEFORE softmax
        mx = fmaxf(mx, mlv[k]);
    }
    float s = 0.f;
    #pragma unroll
    for (int k = 0; k < K; k++) { mlv[k] = expf(mlv[k] - mx); s += mlv[k]; }
    float inv = 1.f / s;

    float acc = 0.f;
    #pragma unroll
    for (int k = 0; k < K; k++) {
        float offv = fp8f(op[(ll)k * Ln]) * 0.0625f;
        float p = (float)l + ((float)k - (float)(K - 1) * 0.5f) + offv;
        float p0 = floorf(p);
        float w = p - p0;
        int i0 = (int)p0;
        float ga = (i0 >= 0 && i0 < Ln) ? __half2float(vp[i0]) : 0.f;
        float gb = (i0 + 1 >= 0 && i0 + 1 < Ln) ? __half2float(vp[i0 + 1]) : 0.f;
        acc += mlv[k] * ((1.f - w) * ga + w * gb);
    }
    dcn[((ll)b * NPn + branch) * ((ll)Cn * Ln) + (ll)c * Ln + l] = __float2half(acc * inv);
}

__global__ void __launch_bounds__(256)
dcnall_k(const u8* __restrict__ offp, const u8* __restrict__ mlp,
         const hf* __restrict__ vp, hf* __restrict__ dcnp)
{
    const ll BCL = (ll)Bn * Cn * Ln;
    switch (blockIdx.y) {
        case 0: dcn_body<7 >(offp, mlp, vp, dcnp, 0, (ll)0 * BCL);  break;
        case 1: dcn_body<9 >(offp, mlp, vp, dcnp, 1, (ll)7 * BCL);  break;
        case 2: dcn_body<11>(offp, mlp, vp, dcnp, 2, (ll)16 * BCL); break;
        case 3: dcn_body<13>(offp, mlp, vp, dcnp, 3, (ll)27 * BCL); break;
        case 4: dcn_body<15>(offp, mlp, vp, dcnp, 4, (ll)40 * BCL); break;
        default: dcn_body<17>(offp, mlp, vp, dcnp, 5, (ll)55 * BCL); break;
    }
}

// ---------------- LayerNorm over C ------------------------------------------
__global__ void __launch_bounds__(256)
ln_k(const float* __restrict__ y, const float* __restrict__ g,
     const float* __restrict__ be, hf* __restrict__ tn)
{
    int l = blockIdx.x * 256 + threadIdx.x;
    int b = blockIdx.y;
    const float* yp = y + (ll)b * Cn * Ln + l;
    float s = 0.f, s2 = 0.f;
    #pragma unroll 8
    for (int c = 0; c < Cn; c++) {
        float v = yp[(ll)c * Ln];
        s += v; s2 += v * v;
    }
    float mu = s * (1.0f / Cn);
    float var = s2 * (1.0f / Cn) - mu * mu;
    float rstd = rsqrtf(var + 1e-6f);
    hf* tp = tn + (ll)b * Cn * Ln + l;
    #pragma unroll 8
    for (int c = 0; c < Cn; c++) {
        float v = yp[(ll)c * Ln];
        tp[(ll)c * Ln] = __float2half((v - mu) * rstd * g[c] + be[c]);
    }
}

// ----------------------------------------------------------------------------
extern "C" void kernel_launch(void* const* d_in, const int* in_sizes, int n_in,
                              void* d_out, int out_size)
{
    const float* x    = (const float*)d_in[0];
    const float* Wa   = (const float*)d_in[1];
    const float* ba   = (const float*)d_in[2];
    const float* Wvd  = (const float*)d_in[3];
    const float* bvd  = (const float*)d_in[4];
    const float* Woff = (const float*)d_in[5];
    const float* boff = (const float*)d_in[6];
    const float* Wm   = (const float*)d_in[7];
    const float* bm   = (const float*)d_in[8];
    const float* Wod  = (const float*)d_in[9];
    const float* bod  = (const float*)d_in[10];
    const float* Wv   = (const float*)d_in[11];
    const float* bv   = (const float*)d_in[12];
    const float* Wp   = (const float*)d_in[13];
    const float* bp   = (const float*)d_in[14];
    const float* ls   = (const float*)d_in[15];
    const float* g2   = (const float*)d_in[16];
    const float* lng  = (const float*)d_in[17];
    const float* lnb  = (const float*)d_in[18];
    const float* W1   = (const float*)d_in[19];
    const float* b1   = (const float*)d_in[20];
    const float* W2   = (const float*)d_in[21];
    const float* b2   = (const float*)d_in[22];
    float* out = (float*)d_out;

    hf *ag, *vvp, *vp, *dcnp, *prodp, *tnp, *hp, *xb;
    hf *wa, *wvd, *wod, *wv, *wp, *woff, *wm, *w1, *w2;
    u8 *offp, *mlp;
    float *yp, *bps;
    cudaGetSymbolAddress((void**)&ag,    g_ag);
    cudaGetSymbolAddress((void**)&vvp,   g_vv);
    cudaGetSymbolAddress((void**)&vp,    g_v);
    cudaGetSymbolAddress((void**)&dcnp,  g_dcn);
    cudaGetSymbolAddress((void**)&prodp, g_prod);
    cudaGetSymbolAddress((void**)&offp,  g_off);
    cudaGetSymbolAddress((void**)&mlp,   g_ml);
    cudaGetSymbolAddress((void**)&yp,    g_y);
    cudaGetSymbolAddress((void**)&tnp,   g_tn);
    cudaGetSymbolAddress((void**)&hp,    g_h);
    cudaGetSymbolAddress((void**)&bps,   g_bps);
    cudaGetSymbolAddress((void**)&wa,    g_wa);
    cudaGetSymbolAddress((void**)&wvd,   g_wvd);
    cudaGetSymbolAddress((void**)&wod,   g_wod);
    cudaGetSymbolAddress((void**)&wv,    g_wv);
    cudaGetSymbolAddress((void**)&wp,    g_wp);
    cudaGetSymbolAddress((void**)&woff,  g_woff);
    cudaGetSymbolAddress((void**)&wm,    g_wm);
    cudaGetSymbolAddress((void**)&w1,    g_w1);
    cudaGetSymbolAddress((void**)&w2,    g_w2);
    cudaGetSymbolAddress((void**)&xb,    g_xb);

    // fused conversions (single launch)
    CvtArgs ca;
    const float* srcs[10] = {x, Wa, Wvd, Wod, Wv, Wp, Woff, Wm, W1, W2};
    hf* dsts[10] = {xb, wa, wvd, wod, wv, wp, woff, wm, w1, w2};
    int cnts[10] = {Bn*Cn*Ln, NPn*Cn*Cn, NPn*Cn*Cn, NPn*Cn*Cn, NPn*Cn*Cn, NPn*Cn*Cn,
                    NPn*KMAXn*Cn*Cn, NPn*KMAXn*Cn*Cn, HIDn*Cn, Cn*HIDn};
    ca.cum[0] = 0;
    for (int i = 0; i < 10; i++) {
        ca.src[i] = srcs[i]; ca.dst[i] = dsts[i];
        ca.cum[i + 1] = ca.cum[i] + cnts[i];
    }
    cvtall_k<<<8192, 256>>>(ca);
    bpsum_k<<<1, 256>>>(bp, bps);

    const ll SB = (ll)NPn * Cn * Ln;
    const ll SI = (ll)Cn * Ln;

    // G1+G2 merged: ag = gelu(Wa@x + ba); vv = Wv@x + bv
    g12_k<<<dim3(4, 24, Bn), 256>>>(wa, ba, wv, bv, xb, ag, vvp);
    // G3: v = Wvd[i]@ag_i + bvd[i]                  (f16 accum)
    gemm_t<0, false, true, hf><<<dim3(4, Cn / 128, NPn * Bn), 256>>>(
        wvd, bvd, ag, vp, Cn, Bn, (ll)Cn * Cn, Cn, SB, SI, SB, SI,
        nullptr, 0, 0, nullptr);
    // G4+G5 fused: off/ml projections -> fp8 e4m3 (x16)
    offml_k<<<dim3(4, 288, Bn), 256>>>(woff, wm, boff, bm, ag, offp, mlp);
    // G6: DCN sampling (fp8 in)
    dcnall_k<<<dim3((Bn * Cn * Ln) / 256, NPn), 256>>>(offp, mlp, vp, dcnp);
    // G7: prod = (Wod[i]@dcn_i + bod[i]) * vv_i      (f16 accum)
    gemm_t<2, false, true, hf><<<dim3(4, Cn / 128, NPn * Bn), 256>>>(
        wod, bod, dcnp, prodp, Cn, Bn, (ll)Cn * Cn, Cn, SB, SI, SB, SI,
        vvp, SB, SI, nullptr);
    // G8: y = x + ls * (sum_i Wp[i]@prod_i + bps)    (f32 accum)
    gemm_t<3, true, false, float><<<dim3(4, Cn / 128, Bn), 256>>>(
        wp, bps, prodp, yp, NPn * Cn, Bn, 0, 0, SB, 0, SI, 0,
        x, SI, 0, ls);
    // G9: LayerNorm
    ln_k<<<dim3(Ln / 256, Bn), 256>>>(yp, lng, lnb, tnp);
    // G10: h = gelu(W1@tn + b1)                      (f16 accum)
    gemm_t<1, false, true, hf><<<dim3(4, HIDn / 128, Bn), 256>>>(
        w1, b1, tnp, hp, Cn, Bn, 0, 0, SI, 0, (ll)HIDn * Ln, 0,
        nullptr, 0, 0, nullptr);
    // G11: out = y + g2 * (W2@h + b2)                (f32 accum)
    gemm_t<3, false, false, float><<<dim3(4, Cn / 128, Bn), 256>>>(
        w2, b2, hp, out, HIDn, Bn, 0, 0, (ll)HIDn * Ln, 0, SI, 0,
        yp, SI, 0, g2);
}

// round 13
// speedup vs baseline: 1.0649x; 1.0649x over previous
#include <cuda_runtime.h>
#include <cuda_fp16.h>
#include <cstdint>
#include <math.h>

#define Bn 8
#define Cn 256
#define Ln 512
#define NPn 6
#define KMAXn 17
#define HIDn 1024
#define SUMK 72

typedef long long ll;
typedef __half hf;

// ---------------- scratch (device globals) ----------------------------------
__device__ __align__(16) hf g_ag  [(size_t)Bn*NPn*Cn*Ln];
__device__ __align__(16) hf g_vv  [(size_t)Bn*NPn*Cn*Ln];
__device__ __align__(16) hf g_v   [(size_t)Bn*NPn*Cn*Ln];
__device__ __align__(16) hf g_dcn [(size_t)Bn*NPn*Cn*Ln];
__device__ __align__(16) hf g_prod[(size_t)Bn*NPn*Cn*Ln];
__device__ __align__(16) hf g_off [(size_t)Bn*Cn*Ln*SUMK];
__device__ __align__(16) hf g_ml  [(size_t)Bn*Cn*Ln*SUMK];
__device__ __align__(16) float g_y [(size_t)Bn*Cn*Ln];
__device__ __align__(16) hf g_tn  [(size_t)Bn*Cn*Ln];
__device__ __align__(16) hf g_h   [(size_t)Bn*HIDn*Ln];
__device__ float g_bps[Cn];
__device__ __align__(16) hf g_wa  [NPn*Cn*Cn];
__device__ __align__(16) hf g_wvd [NPn*Cn*Cn];
__device__ __align__(16) hf g_wod [NPn*Cn*Cn];
__device__ __align__(16) hf g_wv  [NPn*Cn*Cn];
__device__ __align__(16) hf g_wp  [NPn*Cn*Cn];
__device__ __align__(16) hf g_woff[(size_t)NPn*KMAXn*Cn*Cn];
__device__ __align__(16) hf g_wm  [(size_t)NPn*KMAXn*Cn*Cn];
__device__ __align__(16) hf g_w1  [HIDn*Cn];
__device__ __align__(16) hf g_w2  [Cn*HIDn];
__device__ __align__(16) hf g_xb  [(size_t)Bn*Cn*Ln];

__device__ __forceinline__ float gelu_f(float v) {
    return 0.5f * v * (1.0f + erff(v * 0.7071067811865476f));
}

// ---------------- fused conversion --------------------------------------
struct CvtArgs {
    const float* src[10];
    hf* dst[10];
    int cum[11];
};
__global__ void __launch_bounds__(256)
cvtall_k(CvtArgs a)
{
    int total = a.cum[10];
    for (int i = blockIdx.x * 256 + threadIdx.x; i < total; i += gridDim.x * 256) {
        int s = 0;
        #pragma unroll
        for (int j = 1; j < 10; j++) if (i >= a.cum[j]) s = j;
        int off = i - a.cum[s];
        a.dst[s][off] = __float2half(a.src[s][off]);
    }
}

__global__ void bpsum_k(const float* __restrict__ bp, float* __restrict__ out)
{
    int c = threadIdx.x;
    float s = 0.f;
    #pragma unroll
    for (int i = 0; i < NPn; i++) s += bp[i * Cn + c];
    out[c] = s;
}

// ---------------- asm wrappers ----------------------------------------------
__device__ __forceinline__ void cpa16u(uint32_t dst, const void* src) {
    asm volatile("cp.async.cg.shared.global [%0], [%1], 16;\n" :: "r"(dst), "l"(src));
}
__device__ __forceinline__ void ldsm4(uint32_t addr, uint32_t& r0, uint32_t& r1,
                                      uint32_t& r2, uint32_t& r3) {
    asm volatile("ldmatrix.sync.aligned.m8n8.x4.shared.b16 {%0,%1,%2,%3}, [%4];\n"
        : "=r"(r0), "=r"(r1), "=r"(r2), "=r"(r3) : "r"(addr));
}
__device__ __forceinline__ void ldsm4t(uint32_t addr, uint32_t& r0, uint32_t& r1,
                                       uint32_t& r2, uint32_t& r3) {
    asm volatile("ldmatrix.sync.aligned.m8n8.x4.trans.shared.b16 {%0,%1,%2,%3}, [%4];\n"
        : "=r"(r0), "=r"(r1), "=r"(r2), "=r"(r3) : "r"(addr));
}
__device__ __forceinline__ void mma_h32(float& d0, float& d1, float& d2, float& d3,
                                        uint32_t a0, uint32_t a1, uint32_t a2, uint32_t a3,
                                        uint32_t b0, uint32_t b1) {
    asm volatile(
        "mma.sync.aligned.m16n8k16.row.col.f32.f16.f16.f32 "
        "{%0,%1,%2,%3},{%4,%5,%6,%7},{%8,%9},{%0,%1,%2,%3};\n"
        : "+f"(d0), "+f"(d1), "+f"(d2), "+f"(d3)
        : "r"(a0), "r"(a1), "r"(a2), "r"(a3), "r"(b0), "r"(b1));
}
__device__ __forceinline__ void mma_h16(uint32_t& d0, uint32_t& d1,
                                        uint32_t a0, uint32_t a1, uint32_t a2, uint32_t a3,
                                        uint32_t b0, uint32_t b1) {
    asm volatile(
        "mma.sync.aligned.m16n8k16.row.col.f16.f16.f16.f16 "
        "{%0,%1},{%2,%3,%4,%5},{%6,%7},{%0,%1};\n"
        : "+r"(d0), "+r"(d1)
        : "r"(a0), "r"(a1), "r"(a2), "r"(a3), "r"(b0), "r"(b1));
}

// ---------------- GEMM core (128x128 CTA, 8 warps, warp tile 32x64) ----------
template<int EPI, bool STACK, bool ACC16, typename OutT>
__device__ __forceinline__ void gemm_core(
    hf (*As)[128][32], hf (*Bs)[4096],
    const hf* __restrict__ Wz, const float* __restrict__ bz,
    const hf* __restrict__ Xz, OutT* __restrict__ Yz,
    int KDIM, int m0, int n0,
    const void* __restrict__ aux, const float* __restrict__ svec)
{
    const int tid = threadIdx.x, lane = tid & 31, wid = tid >> 5;
    const int wm = wid >> 1, wn = wid & 1;

    float acc[ACC16 ? 1 : 2][8][4];
    uint32_t acch[ACC16 ? 2 : 1][8][2];
    if (!ACC16) {
        #pragma unroll
        for (int i = 0; i < (ACC16 ? 1 : 2); i++)
            #pragma unroll
            for (int j = 0; j < 8; j++)
                #pragma unroll
                for (int q = 0; q < 4; q++) acc[i][j][q] = 0.f;
    } else {
        #pragma unroll
        for (int i = 0; i < (ACC16 ? 2 : 1); i++)
            #pragma unroll
            for (int j = 0; j < 8; j++) { acch[i][j][0] = 0u; acch[i][j][1] = 0u; }
    }

    const uint32_t asBase = (uint32_t)__cvta_generic_to_shared(&As[0][0][0]);
    const uint32_t bBase  = (uint32_t)__cvta_generic_to_shared(&Bs[0][0]);

    const int mA = tid >> 2, cA = tid & 3;
    const int kB = tid >> 4, nB = tid & 15;
    const hf *srcA0, *srcA1;
    if (STACK) {
        srcA0 = Wz + (ll)(m0 + mA) * Cn + cA * 8;
        srcA1 = Wz + (ll)(m0 + mA + 64) * Cn + cA * 8;
    } else {
        srcA0 = Wz + (ll)(m0 + mA) * KDIM + cA * 8;
        srcA1 = Wz + (ll)(m0 + mA + 64) * KDIM + cA * 8;
    }
    const hf* srcB0 = Xz + (ll)kB * Ln + n0 + nB * 8;
    const hf* srcB1 = Xz + (ll)(kB + 16) * Ln + n0 + nB * 8;
    const uint32_t dA0 = asBase + (uint32_t)(mA * 64 + (cA ^ ((mA >> 1) & 3)) * 16);
    const uint32_t dA1 = asBase + (uint32_t)((mA + 64) * 64 + (cA ^ (((mA + 64) >> 1) & 3)) * 16);
    const uint32_t dB0 = bBase + (uint32_t)((kB * 16 + (nB ^ (kB & 7))) * 16);
    const uint32_t dB1 = bBase + (uint32_t)(((kB + 16) * 16 + (nB ^ ((kB + 16) & 7))) * 16);
    int kctr = 0;

    auto loadStage = [&](uint32_t so) {
        cpa16u(dA0 + so, srcA0);
        cpa16u(dA1 + so, srcA1);
        cpa16u(dB0 + so, srcB0);
        cpa16u(dB1 + so, srcB1);
        srcB0 += 32 * Ln; srcB1 += 32 * Ln;
        if (STACK) {
            kctr += 32;
            ll d = 32;
            if ((kctr & 255) == 0) d += (ll)Cn * Cn - 256;
            srcA0 += d; srcA1 += d;
        } else {
            srcA0 += 32; srcA1 += 32;
        }
    };

    uint32_t aAddr[2][2], bAddr[4];
    #pragma unroll
    for (int mt = 0; mt < 2; mt++)
        #pragma unroll
        for (int ks = 0; ks < 2; ks++) {
            int rowp = wm * 32 + mt * 16 + (lane & 15);
            int physA = ((ks * 2) + (lane >> 4)) ^ ((rowp >> 1) & 3);
            aAddr[mt][ks] = asBase + (uint32_t)(rowp * 64 + physA * 16);
        }
    #pragma unroll
    for (int pr = 0; pr < 4; pr++) {
        int phys = (wn * 8 + pr * 2 + (lane >> 4)) ^ (lane & 7);
        bAddr[pr] = bBase + (uint32_t)((lane & 15) * 256 + phys * 16);
    }

    const int nIt = KDIM >> 5;
    loadStage(0);
    asm volatile("cp.async.commit_group;\n");
    loadStage(8192);
    asm volatile("cp.async.commit_group;\n");

    uint32_t ldSlot = 16384, sOff = 0;
    for (int it = 0; it < nIt; it++) {
        if (it + 1 < nIt) asm volatile("cp.async.wait_group 1;\n");
        else              asm volatile("cp.async.wait_group 0;\n");
        __syncthreads();
        if (it + 2 < nIt) {
            loadStage(ldSlot);
            ldSlot = (ldSlot == 16384) ? 0 : ldSlot + 8192;
        }
        asm volatile("cp.async.commit_group;\n");

        #pragma unroll
        for (int ks = 0; ks < 2; ks++) {
            uint32_t fa[2][4];
            {
                uint32_t t0, t1, t2, t3;
                ldsm4(aAddr[0][ks] + sOff, t0, t1, t2, t3);
                fa[0][0] = t0; fa[0][1] = t1; fa[0][2] = t2; fa[0][3] = t3;
                ldsm4(aAddr[1][ks] + sOff, t0, t1, t2, t3);
                fa[1][0] = t0; fa[1][1] = t1; fa[1][2] = t2; fa[1][3] = t3;
            }
            uint32_t fb[4][4];
            #pragma unroll
            for (int pr = 0; pr < 4; pr++) {
                uint32_t t0, t1, t2, t3;
                ldsm4t(bAddr[pr] + (uint32_t)(ks * 4096) + sOff, t0, t1, t2, t3);
                fb[pr][0] = t0; fb[pr][1] = t1; fb[pr][2] = t2; fb[pr][3] = t3;
            }
            #pragma unroll
            for (int mt = 0; mt < 2; mt++)
                #pragma unroll
                for (int nt = 0; nt < 8; nt++) {
                    if (ACC16) {
                        uint32_t c0 = acch[mt][nt][0], c1 = acch[mt][nt][1];
                        mma_h16(c0, c1,
                                fa[mt][0], fa[mt][1], fa[mt][2], fa[mt][3],
                                fb[nt >> 1][(nt & 1) * 2], fb[nt >> 1][(nt & 1) * 2 + 1]);
                        acch[mt][nt][0] = c0; acch[mt][nt][1] = c1;
                    } else {
                        float c0 = acc[mt][nt][0], c1 = acc[mt][nt][1];
                        float c2 = acc[mt][nt][2], c3 = acc[mt][nt][3];
                        mma_h32(c0, c1, c2, c3,
                                fa[mt][0], fa[mt][1], fa[mt][2], fa[mt][3],
                                fb[nt >> 1][(nt & 1) * 2], fb[nt >> 1][(nt & 1) * 2 + 1]);
                        acc[mt][nt][0] = c0; acc[mt][nt][1] = c1;
                        acc[mt][nt][2] = c2; acc[mt][nt][3] = c3;
                    }
                }
        }
        sOff = (sOff == 16384) ? 0 : sOff + 8192;
    }

    // epilogue
    const int row = lane >> 2, colp = (lane & 3) * 2;
    #pragma unroll
    for (int mt = 0; mt < 2; mt++) {
        #pragma unroll
        for (int h = 0; h < 2; h++) {
            int o = m0 + wm * 32 + mt * 16 + row + h * 8;
            float bb = bz[o];
            float sv = (EPI == 3) ? svec[o] : 0.f;
            #pragma unroll
            for (int nt = 0; nt < 8; nt++) {
                int l = n0 + wn * 64 + nt * 8 + colp;
                ll yi = (ll)o * Ln + l;
                float r0, r1;
                if (ACC16) {
                    __half2 hv = *(__half2*)&acch[mt][nt][h];
                    r0 = __low2float(hv) + bb;
                    r1 = __high2float(hv) + bb;
                } else {
                    r0 = acc[mt][nt][h * 2 + 0] + bb;
                    r1 = acc[mt][nt][h * 2 + 1] + bb;
                }
                if (EPI == 1) { r0 = gelu_f(r0); r1 = gelu_f(r1); }
                if (EPI == 2) {
                    __half2 av = *(const __half2*)(((const hf*)aux) + yi);
                    r0 *= __low2float(av); r1 *= __high2float(av);
                }
                if (EPI == 3) {
                    float2 av = *(const float2*)(((const float*)aux) + yi);
                    r0 = av.x + sv * r0; r1 = av.y + sv * r1;
                }
                if (sizeof(OutT) == 2) {
                    __half2 pv = __floats2half2_rn(r0, r1);
                    *(__half2*)((hf*)Yz + yi) = pv;
                } else {
                    float2 fv; fv.x = r0; fv.y = r1;
                    *(float2*)((float*)Yz + yi) = fv;
                }
            }
        }
    }
}

// ---------------- generic GEMM kernel wrapper --------------------------------
template<int EPI, bool STACK, bool ACC16, typename OutT>
__global__ void __launch_bounds__(256, 2)
gemm_t(const hf* __restrict__ W, const float* __restrict__ bias,
       const hf* __restrict__ X, OutT* __restrict__ Y,
       int KDIM, int zB,
       ll wStrideI, int bStrideI,
       ll xStrideB, ll xStrideI,
       ll yStrideB, ll yStrideI,
       const void* __restrict__ aux, ll aStrideB, ll aStrideI,
       const float* __restrict__ svec)
{
    __shared__ __align__(16) hf As[3][128][32];
    __shared__ __align__(16) hf Bs[3][4096];
    const int z = blockIdx.z;
    const int b = z % zB, br = z / zB;
    const hf*  Wz = W + (ll)br * wStrideI;
    const float* bz = bias + (ll)br * bStrideI;
    const hf*  Xz = X + (ll)b * xStrideB + (ll)br * xStrideI;
    OutT* Yz = Y + (ll)b * yStrideB + (ll)br * yStrideI;
    const void* auxp = nullptr;
    if (EPI == 2) auxp = ((const hf*)aux) + (ll)b * aStrideB + (ll)br * aStrideI;
    if (EPI == 3) auxp = ((const float*)aux) + (ll)b * aStrideB + (ll)br * aStrideI;
    gemm_core<EPI, STACK, ACC16, OutT>(As, Bs, Wz, bz, Xz, Yz, KDIM,
                                       blockIdx.y * 128, blockIdx.x * 128, auxp, svec);
}

// ---------------- merged G1+G2 kernel -----------------------------------------
__global__ void __launch_bounds__(256, 2)
g12_k(const hf* __restrict__ wa, const float* __restrict__ ba,
      const hf* __restrict__ wv, const float* __restrict__ bv,
      const hf* __restrict__ xb, hf* __restrict__ ag, hf* __restrict__ vvp)
{
    __shared__ __align__(16) hf As[3][128][32];
    __shared__ __align__(16) hf Bs[3][4096];
    int t = blockIdx.y;
    int b = blockIdx.z;
    const ll SB = (ll)NPn * Cn * Ln;
    const hf* Xz = xb + (ll)b * Cn * Ln;
    if (t < 12) {
        gemm_core<1, false, true, hf>(As, Bs, wa, ba, Xz, ag + (ll)b * SB, Cn,
                                      t * 128, blockIdx.x * 128, nullptr, nullptr);
    } else {
        gemm_core<0, false, true, hf>(As, Bs, wv, bv, Xz, vvp + (ll)b * SB, Cn,
                                      (t - 12) * 128, blockIdx.x * 128, nullptr, nullptr);
    }
}

// ---------------- fused off+ml mega-GEMM (fp16 out) ---------------------------
__global__ void __launch_bounds__(256, 2)
offml_k(const hf* __restrict__ woff, const hf* __restrict__ wm,
        const float* __restrict__ boff, const float* __restrict__ bm,
        const hf* __restrict__ ag, hf* __restrict__ offp, hf* __restrict__ mlp)
{
    __shared__ __align__(16) hf As[3][128][32];
    __shared__ __align__(16) hf Bs[3][4096];
    const int bnd[7]  = {0, 14, 32, 54, 80, 110, 144};
    const int preK[6] = {0, 7, 16, 27, 40, 55};
    int t = blockIdx.y;
    int b = blockIdx.z;
    int kind = (t >= 144) ? 1 : 0;
    int tt = t - kind * 144;
    int br = 0;
    #pragma unroll
    for (int j = 1; j < 6; j++) if (tt >= bnd[j]) br = j;
    int mloc = (tt - bnd[br]) * 128;
    int K = 7 + 2 * br;
    const hf*    W  = (kind ? wm : woff) + (ll)br * KMAXn * Cn * Cn + (ll)mloc * Cn;
    const float* bz = (kind ? bm : boff) + br * KMAXn * Cn + mloc;
    const hf*    Xz = ag + ((ll)b * NPn + br) * ((ll)Cn * Ln);
    hf* Y = (kind ? mlp : offp) + (ll)preK[br] * ((ll)Bn * Cn * Ln)
            + (ll)b * Cn * K * Ln + (ll)mloc * Ln;
    gemm_core<0, false, true, hf>(As, Bs, W, bz, Xz, Y, Cn, 0, blockIdx.x * 128,
                                  nullptr, nullptr);
}

// ---------------- DCN (all branches, one launch) -------------------------------
template<int K>
__device__ __forceinline__ void dcn_body(
    const hf* __restrict__ off_all, const hf* __restrict__ ml_all,
    const hf* __restrict__ v_all, hf* __restrict__ dcn,
    int branch, ll regionBase)
{
    ll idx = (ll)blockIdx.x * 256 + threadIdx.x;
    int l = (int)(idx & (Ln - 1));
    int c = (int)((idx >> 9) & (Cn - 1));
    int b = (int)(idx >> 17);
    ll rowBase = regionBase + ((ll)b * Cn * K + (ll)c * K) * Ln + l;
    const hf* op = off_all + rowBase;
    const hf* mp = ml_all + rowBase;
    const hf* vp = v_all + ((ll)b * NPn + branch) * ((ll)Cn * Ln) + (ll)c * Ln;

    float mlv[K];
    float mx = -3.4e38f;
    #pragma unroll
    for (int k = 0; k < K; k++) { mlv[k] = __half2float(mp[(ll)k * Ln]); mx = fmaxf(mx, mlv[k]); }
    float s = 0.f;
    #pragma unroll
    for (int k = 0; k < K; k++) { mlv[k] = expf(mlv[k] - mx); s += mlv[k]; }
    float inv = 1.f / s;

    float acc = 0.f;
    #pragma unroll
    for (int k = 0; k < K; k++) {
        float p = (float)l + ((float)k - (float)(K - 1) * 0.5f) + __half2float(op[(ll)k * Ln]);
        float p0 = floorf(p);
        float w = p - p0;
        int i0 = (int)p0;
        float ga = (i0 >= 0 && i0 < Ln) ? __half2float(vp[i0]) : 0.f;
        float gb = (i0 + 1 >= 0 && i0 + 1 < Ln) ? __half2float(vp[i0 + 1]) : 0.f;
        acc += mlv[k] * ((1.f - w) * ga + w * gb);
    }
    dcn[((ll)b * NPn + branch) * ((ll)Cn * Ln) + (ll)c * Ln + l] = __float2half(acc * inv);
}

__global__ void __launch_bounds__(256)
dcnall_k(const hf* __restrict__ offp, const hf* __restrict__ mlp,
         const hf* __restrict__ vp, hf* __restrict__ dcnp)
{
    const ll BCL = (ll)Bn * Cn * Ln;
    switch (blockIdx.y) {
        case 0: dcn_body<7 >(offp, mlp, vp, dcnp, 0, (ll)0 * BCL);  break;
        case 1: dcn_body<9 >(offp, mlp, vp, dcnp, 1, (ll)7 * BCL);  break;
        case 2: dcn_body<11>(offp, mlp, vp, dcnp, 2, (ll)16 * BCL); break;
        case 3: dcn_body<13>(offp, mlp, vp, dcnp, 3, (ll)27 * BCL); break;
        case 4: dcn_body<15>(offp, mlp, vp, dcnp, 4, (ll)40 * BCL); break;
        default: dcn_body<17>(offp, mlp, vp, dcnp, 5, (ll)55 * BCL); break;
    }
}

// ---------------- LayerNorm over C ------------------------------------------
__global__ void __launch_bounds__(256)
ln_k(const float* __restrict__ y, const float* __restrict__ g,
     const float* __restrict__ be, hf* __restrict__ tn)
{
    int l = blockIdx.x * 256 + threadIdx.x;
    int b = blockIdx.y;
    const float* yp = y + (ll)b * Cn * Ln + l;
    float s = 0.f, s2 = 0.f;
    #pragma unroll 8
    for (int c = 0; c < Cn; c++) {
        float v = yp[(ll)c * Ln];
        s += v; s2 += v * v;
    }
    float mu = s * (1.0f / Cn);
    float var = s2 * (1.0f / Cn) - mu * mu;
    float rstd = rsqrtf(var + 1e-6f);
    hf* tp = tn + (ll)b * Cn * Ln + l;
    #pragma unroll 8
    for (int c = 0; c < Cn; c++) {
        float v = yp[(ll)c * Ln];
        tp[(ll)c * Ln] = __float2half((v - mu) * rstd * g[c] + be[c]);
    }
}

// ----------------------------------------------------------------------------
extern "C" void kernel_launch(void* const* d_in, const int* in_sizes, int n_in,
                              void* d_out, int out_size)
{
    const float* x    = (const float*)d_in[0];
    const float* Wa   = (const float*)d_in[1];
    const float* ba   = (const float*)d_in[2];
    const float* Wvd  = (const float*)d_in[3];
    const float* bvd  = (const float*)d_in[4];
    const float* Woff = (const float*)d_in[5];
    const float* boff = (const float*)d_in[6];
    const float* Wm   = (const float*)d_in[7];
    const float* bm   = (const float*)d_in[8];
    const float* Wod  = (const float*)d_in[9];
    const float* bod  = (const float*)d_in[10];
    const float* Wv   = (const float*)d_in[11];
    const float* bv   = (const float*)d_in[12];
    const float* Wp   = (const float*)d_in[13];
    const float* bp   = (const float*)d_in[14];
    const float* ls   = (const float*)d_in[15];
    const float* g2   = (const float*)d_in[16];
    const float* lng  = (const float*)d_in[17];
    const float* lnb  = (const float*)d_in[18];
    const float* W1   = (const float*)d_in[19];
    const float* b1   = (const float*)d_in[20];
    const float* W2   = (const float*)d_in[21];
    const float* b2   = (const float*)d_in[22];
    float* out = (float*)d_out;

    hf *ag, *vvp, *vp, *dcnp, *prodp, *offp, *mlp, *tnp, *hp, *xb;
    hf *wa, *wvd, *wod, *wv, *wp, *woff, *wm, *w1, *w2;
    float *yp, *bps;
    cudaGetSymbolAddress((void**)&ag,    g_ag);
    cudaGetSymbolAddress((void**)&vvp,   g_vv);
    cudaGetSymbolAddress((void**)&vp,    g_v);
    cudaGetSymbolAddress((void**)&dcnp,  g_dcn);
    cudaGetSymbolAddress((void**)&prodp, g_prod);
    cudaGetSymbolAddress((void**)&offp,  g_off);
    cudaGetSymbolAddress((void**)&mlp,   g_ml);
    cudaGetSymbolAddress((void**)&yp,    g_y);
    cudaGetSymbolAddress((void**)&tnp,   g_tn);
    cudaGetSymbolAddress((void**)&hp,    g_h);
    cudaGetSymbolAddress((void**)&bps,   g_bps);
    cudaGetSymbolAddress((void**)&wa,    g_wa);
    cudaGetSymbolAddress((void**)&wvd,   g_wvd);
    cudaGetSymbolAddress((void**)&wod,   g_wod);
    cudaGetSymbolAddress((void**)&wv,    g_wv);
    cudaGetSymbolAddress((void**)&wp,    g_wp);
    cudaGetSymbolAddress((void**)&woff,  g_woff);
    cudaGetSymbolAddress((void**)&wm,    g_wm);
    cudaGetSymbolAddress((void**)&w1,    g_w1);
    cudaGetSymbolAddress((void**)&w2,    g_w2);
    cudaGetSymbolAddress((void**)&xb,    g_xb);

    // fused conversions (single launch)
    CvtArgs ca;
    const float* srcs[10] = {x, Wa, Wvd, Wod, Wv, Wp, Woff, Wm, W1, W2};
    hf* dsts[10] = {xb, wa, wvd, wod, wv, wp, woff, wm, w1, w2};
    int cnts[10] = {Bn*Cn*Ln, NPn*Cn*Cn, NPn*Cn*Cn, NPn*Cn*Cn, NPn*Cn*Cn, NPn*Cn*Cn,
                    NPn*KMAXn*Cn*Cn, NPn*KMAXn*Cn*Cn, HIDn*Cn, Cn*HIDn};
    ca.cum[0] = 0;
    for (int i = 0; i < 10; i++) {
        ca.src[i] = srcs[i]; ca.dst[i] = dsts[i];
        ca.cum[i + 1] = ca.cum[i] + cnts[i];
    }
    cvtall_k<<<8192, 256>>>(ca);
    bpsum_k<<<1, 256>>>(bp, bps);

    const ll SB = (ll)NPn * Cn * Ln;
    const ll SI = (ll)Cn * Ln;

    // G1+G2 merged: ag = gelu(Wa@x + ba); vv = Wv@x + bv   (f16 accum)
    g12_k<<<dim3(4, 24, Bn), 256>>>(wa, ba, wv, bv, xb, ag, vvp);
    // G3: v = Wvd[i]@ag_i + bvd[i]                  (f16 accum)
    gemm_t<0, false, true, hf><<<dim3(4, Cn / 128, NPn * Bn), 256>>>(
        wvd, bvd, ag, vp, Cn, Bn, (ll)Cn * Cn, Cn, SB, SI, SB, SI,
        nullptr, 0, 0, nullptr);
    // G4+G5 fused: off/ml projections                (f16 accum, fp16 out)
    offml_k<<<dim3(4, 288, Bn), 256>>>(woff, wm, boff, bm, ag, offp, mlp);
    // G6: DCN sampling (one launch, 6 branches)
    dcnall_k<<<dim3((Bn * Cn * Ln) / 256, NPn), 256>>>(offp, mlp, vp, dcnp);
    // G7: prod = (Wod[i]@dcn_i + bod[i]) * vv_i      (f16 accum)
    gemm_t<2, false, true, hf><<<dim3(4, Cn / 128, NPn * Bn), 256>>>(
        wod, bod, dcnp, prodp, Cn, Bn, (ll)Cn * Cn, Cn, SB, SI, SB, SI,
        vvp, SB, SI, nullptr);
    // G8: y = x + ls * (sum_i Wp[i]@prod_i + bps)    (f32 accum)
    gemm_t<3, true, false, float><<<dim3(4, Cn / 128, Bn), 256>>>(
        wp, bps, prodp, yp, NPn * Cn, Bn, 0, 0, SB, 0, SI, 0,
        x, SI, 0, ls);
    // G9: LayerNorm
    ln_k<<<dim3(Ln / 256, Bn), 256>>>(yp, lng, lnb, tnp);
    // G10: h = gelu(W1@tn + b1)                      (f16 accum)
    gemm_t<1, false, true, hf><<<dim3(4, HIDn / 128, Bn), 256>>>(
        w1, b1, tnp, hp, Cn, Bn, 0, 0, SI, 0, (ll)HIDn * Ln, 0,
        nullptr, 0, 0, nullptr);
    // G11: out = y + g2 * (W2@h + b2)                (f32 accum)
    gemm_t<3, false, false, float><<<dim3(4, Cn / 128, Bn), 256>>>(
        w2, b2, hp, out, HIDn, Bn, 0, 0, (ll)HIDn * Ln, 0, SI, 0,
        yp, SI, 0, g2);
}

// round 14
// speedup vs baseline: 1.0910x; 1.0245x over previous
#include <cuda_runtime.h>
#include <cuda_fp16.h>
#include <cstdint>
#include <math.h>

#define Bn 8
#define Cn 256
#define Ln 512
#define NPn 6
#define KMAXn 17
#define HIDn 1024
#define SUMK 72
#define BCL ((ll)Bn*Cn*Ln)

typedef long long ll;
typedef __half hf;

// ---------------- scratch (device globals) ----------------------------------
__device__ __align__(16) hf g_ag  [(size_t)Bn*NPn*Cn*Ln];
__device__ __align__(16) hf g_vv  [(size_t)Bn*NPn*Cn*Ln];
__device__ __align__(16) hf g_v   [(size_t)Bn*NPn*Cn*Ln];
__device__ __align__(16) hf g_dcn [(size_t)Bn*NPn*Cn*Ln];
__device__ __align__(16) hf g_prod[(size_t)Bn*NPn*Cn*Ln];
__device__ __align__(16) hf g_off [(size_t)Bn*Cn*Ln*SUMK];
__device__ __align__(16) hf g_ml  [(size_t)Bn*Cn*Ln*SUMK];
__device__ __align__(16) float g_y [(size_t)Bn*Cn*Ln];
__device__ __align__(16) hf g_tn  [(size_t)Bn*Cn*Ln];
__device__ __align__(16) hf g_h   [(size_t)Bn*HIDn*Ln];
__device__ __align__(16) float g_part[(size_t)6*Bn*Cn*Ln];
__device__ float g_bps[Cn];
__device__ __align__(16) hf g_wa  [NPn*Cn*Cn];
__device__ __align__(16) hf g_wvd [NPn*Cn*Cn];
__device__ __align__(16) hf g_wod [NPn*Cn*Cn];
__device__ __align__(16) hf g_wv  [NPn*Cn*Cn];
__device__ __align__(16) hf g_wp  [NPn*Cn*Cn];
__device__ __align__(16) hf g_woff[(size_t)NPn*KMAXn*Cn*Cn];
__device__ __align__(16) hf g_wm  [(size_t)NPn*KMAXn*Cn*Cn];
__device__ __align__(16) hf g_w1  [HIDn*Cn];
__device__ __align__(16) hf g_w2  [Cn*HIDn];
__device__ __align__(16) hf g_xb  [(size_t)Bn*Cn*Ln];

__device__ __forceinline__ float gelu_f(float v) {
    return 0.5f * v * (1.0f + erff(v * 0.7071067811865476f));
}

// ---------------- fused conversion --------------------------------------
struct CvtArgs {
    const float* src[10];
    hf* dst[10];
    int cum[11];
};
__global__ void __launch_bounds__(256)
cvtall_k(CvtArgs a)
{
    int total = a.cum[10];
    for (int i = blockIdx.x * 256 + threadIdx.x; i < total; i += gridDim.x * 256) {
        int s = 0;
        #pragma unroll
        for (int j = 1; j < 10; j++) if (i >= a.cum[j]) s = j;
        int off = i - a.cum[s];
        a.dst[s][off] = __float2half(a.src[s][off]);
    }
}

__global__ void bpsum_k(const float* __restrict__ bp, float* __restrict__ out)
{
    int c = threadIdx.x;
    float s = 0.f;
    #pragma unroll
    for (int i = 0; i < NPn; i++) s += bp[i * Cn + c];
    out[c] = s;
}

// ---------------- asm wrappers ----------------------------------------------
__device__ __forceinline__ void cpa16u(uint32_t dst, const void* src) {
    asm volatile("cp.async.cg.shared.global [%0], [%1], 16;\n" :: "r"(dst), "l"(src));
}
__device__ __forceinline__ void ldsm4(uint32_t addr, uint32_t& r0, uint32_t& r1,
                                      uint32_t& r2, uint32_t& r3) {
    asm volatile("ldmatrix.sync.aligned.m8n8.x4.shared.b16 {%0,%1,%2,%3}, [%4];\n"
        : "=r"(r0), "=r"(r1), "=r"(r2), "=r"(r3) : "r"(addr));
}
__device__ __forceinline__ void ldsm4t(uint32_t addr, uint32_t& r0, uint32_t& r1,
                                       uint32_t& r2, uint32_t& r3) {
    asm volatile("ldmatrix.sync.aligned.m8n8.x4.trans.shared.b16 {%0,%1,%2,%3}, [%4];\n"
        : "=r"(r0), "=r"(r1), "=r"(r2), "=r"(r3) : "r"(addr));
}
__device__ __forceinline__ void mma_h32(float& d0, float& d1, float& d2, float& d3,
                                        uint32_t a0, uint32_t a1, uint32_t a2, uint32_t a3,
                                        uint32_t b0, uint32_t b1) {
    asm volatile(
        "mma.sync.aligned.m16n8k16.row.col.f32.f16.f16.f32 "
        "{%0,%1,%2,%3},{%4,%5,%6,%7},{%8,%9},{%0,%1,%2,%3};\n"
        : "+f"(d0), "+f"(d1), "+f"(d2), "+f"(d3)
        : "r"(a0), "r"(a1), "r"(a2), "r"(a3), "r"(b0), "r"(b1));
}
__device__ __forceinline__ void mma_h16(uint32_t& d0, uint32_t& d1,
                                        uint32_t a0, uint32_t a1, uint32_t a2, uint32_t a3,
                                        uint32_t b0, uint32_t b1) {
    asm volatile(
        "mma.sync.aligned.m16n8k16.row.col.f16.f16.f16.f16 "
        "{%0,%1},{%2,%3,%4,%5},{%6,%7},{%0,%1};\n"
        : "+r"(d0), "+r"(d1)
        : "r"(a0), "r"(a1), "r"(a2), "r"(a3), "r"(b0), "r"(b1));
}

// ---------------- GEMM core (128x128 CTA, 8 warps, warp tile 32x64) ----------
// EPI: 0 none, 1 gelu, 2 *aux(hf), 3 aux(f32)+svec*(.), 5 raw f32 store (no bias)
template<int EPI, bool ACC16, typename OutT>
__device__ __forceinline__ void gemm_core(
    hf (*As)[128][32], hf (*Bs)[4096],
    const hf* __restrict__ Wz, const float* __restrict__ bz,
    const hf* __restrict__ Xz, OutT* __restrict__ Yz,
    int KDIM, int wLD, int m0, int n0,
    const void* __restrict__ aux, const float* __restrict__ svec)
{
    const int tid = threadIdx.x, lane = tid & 31, wid = tid >> 5;
    const int wm = wid >> 1, wn = wid & 1;

    float acc[ACC16 ? 1 : 2][8][4];
    uint32_t acch[ACC16 ? 2 : 1][8][2];
    if (!ACC16) {
        #pragma unroll
        for (int i = 0; i < (ACC16 ? 1 : 2); i++)
            #pragma unroll
            for (int j = 0; j < 8; j++)
                #pragma unroll
                for (int q = 0; q < 4; q++) acc[i][j][q] = 0.f;
    } else {
        #pragma unroll
        for (int i = 0; i < (ACC16 ? 2 : 1); i++)
            #pragma unroll
            for (int j = 0; j < 8; j++) { acch[i][j][0] = 0u; acch[i][j][1] = 0u; }
    }

    const uint32_t asBase = (uint32_t)__cvta_generic_to_shared(&As[0][0][0]);
    const uint32_t bBase  = (uint32_t)__cvta_generic_to_shared(&Bs[0][0]);

    const int mA = tid >> 2, cA = tid & 3;
    const int kB = tid >> 4, nB = tid & 15;
    const hf* srcA0 = Wz + (ll)(m0 + mA) * wLD + cA * 8;
    const hf* srcA1 = Wz + (ll)(m0 + mA + 64) * wLD + cA * 8;
    const hf* srcB0 = Xz + (ll)kB * Ln + n0 + nB * 8;
    const hf* srcB1 = Xz + (ll)(kB + 16) * Ln + n0 + nB * 8;
    const uint32_t dA0 = asBase + (uint32_t)(mA * 64 + (cA ^ ((mA >> 1) & 3)) * 16);
    const uint32_t dA1 = asBase + (uint32_t)((mA + 64) * 64 + (cA ^ (((mA + 64) >> 1) & 3)) * 16);
    const uint32_t dB0 = bBase + (uint32_t)((kB * 16 + (nB ^ (kB & 7))) * 16);
    const uint32_t dB1 = bBase + (uint32_t)(((kB + 16) * 16 + (nB ^ ((kB + 16) & 7))) * 16);

    auto loadStage = [&](uint32_t so) {
        cpa16u(dA0 + so, srcA0);
        cpa16u(dA1 + so, srcA1);
        cpa16u(dB0 + so, srcB0);
        cpa16u(dB1 + so, srcB1);
        srcB0 += 32 * Ln; srcB1 += 32 * Ln;
        srcA0 += 32; srcA1 += 32;
    };

    uint32_t aAddr[2][2], bAddr[4];
    #pragma unroll
    for (int mt = 0; mt < 2; mt++)
        #pragma unroll
        for (int ks = 0; ks < 2; ks++) {
            int rowp = wm * 32 + mt * 16 + (lane & 15);
            int physA = ((ks * 2) + (lane >> 4)) ^ ((rowp >> 1) & 3);
            aAddr[mt][ks] = asBase + (uint32_t)(rowp * 64 + physA * 16);
        }
    #pragma unroll
    for (int pr = 0; pr < 4; pr++) {
        int phys = (wn * 8 + pr * 2 + (lane >> 4)) ^ (lane & 7);
        bAddr[pr] = bBase + (uint32_t)((lane & 15) * 256 + phys * 16);
    }

    const int nIt = KDIM >> 5;
    loadStage(0);
    asm volatile("cp.async.commit_group;\n");
    loadStage(8192);
    asm volatile("cp.async.commit_group;\n");

    uint32_t ldSlot = 16384, sOff = 0;
    for (int it = 0; it < nIt; it++) {
        if (it + 1 < nIt) asm volatile("cp.async.wait_group 1;\n");
        else              asm volatile("cp.async.wait_group 0;\n");
        __syncthreads();
        if (it + 2 < nIt) {
            loadStage(ldSlot);
            ldSlot = (ldSlot == 16384) ? 0 : ldSlot + 8192;
        }
        asm volatile("cp.async.commit_group;\n");

        #pragma unroll
        for (int ks = 0; ks < 2; ks++) {
            uint32_t fa[2][4];
            {
                uint32_t t0, t1, t2, t3;
                ldsm4(aAddr[0][ks] + sOff, t0, t1, t2, t3);
                fa[0][0] = t0; fa[0][1] = t1; fa[0][2] = t2; fa[0][3] = t3;
                ldsm4(aAddr[1][ks] + sOff, t0, t1, t2, t3);
                fa[1][0] = t0; fa[1][1] = t1; fa[1][2] = t2; fa[1][3] = t3;
            }
            uint32_t fb[4][4];
            #pragma unroll
            for (int pr = 0; pr < 4; pr++) {
                uint32_t t0, t1, t2, t3;
                ldsm4t(bAddr[pr] + (uint32_t)(ks * 4096) + sOff, t0, t1, t2, t3);
                fb[pr][0] = t0; fb[pr][1] = t1; fb[pr][2] = t2; fb[pr][3] = t3;
            }
            #pragma unroll
            for (int mt = 0; mt < 2; mt++)
                #pragma unroll
                for (int nt = 0; nt < 8; nt++) {
                    if (ACC16) {
                        uint32_t c0 = acch[mt][nt][0], c1 = acch[mt][nt][1];
                        mma_h16(c0, c1,
                                fa[mt][0], fa[mt][1], fa[mt][2], fa[mt][3],
                                fb[nt >> 1][(nt & 1) * 2], fb[nt >> 1][(nt & 1) * 2 + 1]);
                        acch[mt][nt][0] = c0; acch[mt][nt][1] = c1;
                    } else {
                        float c0 = acc[mt][nt][0], c1 = acc[mt][nt][1];
                        float c2 = acc[mt][nt][2], c3 = acc[mt][nt][3];
                        mma_h32(c0, c1, c2, c3,
                                fa[mt][0], fa[mt][1], fa[mt][2], fa[mt][3],
                                fb[nt >> 1][(nt & 1) * 2], fb[nt >> 1][(nt & 1) * 2 + 1]);
                        acc[mt][nt][0] = c0; acc[mt][nt][1] = c1;
                        acc[mt][nt][2] = c2; acc[mt][nt][3] = c3;
                    }
                }
        }
        sOff = (sOff == 16384) ? 0 : sOff + 8192;
    }

    // epilogue
    const int row = lane >> 2, colp = (lane & 3) * 2;
    #pragma unroll
    for (int mt = 0; mt < 2; mt++) {
        #pragma unroll
        for (int h = 0; h < 2; h++) {
            int o = m0 + wm * 32 + mt * 16 + row + h * 8;
            float bb = (EPI == 5) ? 0.f : bz[o];
            float sv = (EPI == 3) ? svec[o] : 0.f;
            #pragma unroll
            for (int nt = 0; nt < 8; nt++) {
                int l = n0 + wn * 64 + nt * 8 + colp;
                ll yi = (ll)o * Ln + l;
                float r0, r1;
                if (ACC16) {
                    __half2 hv = *(__half2*)&acch[mt][nt][h];
                    r0 = __low2float(hv) + bb;
                    r1 = __high2float(hv) + bb;
                } else {
                    r0 = acc[mt][nt][h * 2 + 0] + bb;
                    r1 = acc[mt][nt][h * 2 + 1] + bb;
                }
                if (EPI == 1) { r0 = gelu_f(r0); r1 = gelu_f(r1); }
                if (EPI == 2) {
                    __half2 av = *(const __half2*)(((const hf*)aux) + yi);
                    r0 *= __low2float(av); r1 *= __high2float(av);
                }
                if (EPI == 3) {
                    float2 av = *(const float2*)(((const float*)aux) + yi);
                    r0 = av.x + sv * r0; r1 = av.y + sv * r1;
                }
                if (sizeof(OutT) == 2) {
                    __half2 pv = __floats2half2_rn(r0, r1);
                    *(__half2*)((hf*)Yz + yi) = pv;
                } else {
                    float2 fv; fv.x = r0; fv.y = r1;
                    *(float2*)((float*)Yz + yi) = fv;
                }
            }
        }
    }
}

// ---------------- generic GEMM kernel wrapper --------------------------------
template<int EPI, bool ACC16, typename OutT>
__global__ void __launch_bounds__(256, 2)
gemm_t(const hf* __restrict__ W, const float* __restrict__ bias,
       const hf* __restrict__ X, OutT* __restrict__ Y,
       int KDIM, int zB,
       ll wStrideI, int bStrideI,
       ll xStrideB, ll xStrideI,
       ll yStrideB, ll yStrideI,
       const void* __restrict__ aux, ll aStrideB, ll aStrideI,
       const float* __restrict__ svec)
{
    __shared__ __align__(16) hf As[3][128][32];
    __shared__ __align__(16) hf Bs[3][4096];
    const int z = blockIdx.z;
    const int b = z % zB, br = z / zB;
    const hf*  Wz = W + (ll)br * wStrideI;
    const float* bz = bias + (ll)br * bStrideI;
    const hf*  Xz = X + (ll)b * xStrideB + (ll)br * xStrideI;
    OutT* Yz = Y + (ll)b * yStrideB + (ll)br * yStrideI;
    const void* auxp = nullptr;
    if (EPI == 2) auxp = ((const hf*)aux) + (ll)b * aStrideB + (ll)br * aStrideI;
    if (EPI == 3) auxp = ((const float*)aux) + (ll)b * aStrideB + (ll)br * aStrideI;
    gemm_core<EPI, ACC16, OutT>(As, Bs, Wz, bz, Xz, Yz, KDIM, KDIM,
                                blockIdx.y * 128, blockIdx.x * 128, auxp, svec);
}

// ---------------- split-K partial GEMM ---------------------------------------
__global__ void __launch_bounds__(256, 2)
gpart_k(const hf* __restrict__ W, int wLD, ll wChunk,
        const hf* __restrict__ X, ll xStrideB, ll xChunk,
        float* __restrict__ parts)
{
    __shared__ __align__(16) hf As[3][128][32];
    __shared__ __align__(16) hf Bs[3][4096];
    int z = blockIdx.z;
    int b = z % Bn, ch = z / Bn;
    const hf* Wz = W + (ll)ch * wChunk;
    const hf* Xz = X + (ll)b * xStrideB + (ll)ch * xChunk;
    float* Yz = parts + (ll)ch * BCL + (ll)b * Cn * Ln;
    gemm_core<5, false, float>(As, Bs, Wz, nullptr, Xz, Yz, 256, wLD,
                               blockIdx.y * 128, blockIdx.x * 128, nullptr, nullptr);
}

// ---------------- split-K epilogue: out = aux + svec*(sum(parts) + bias) ------
template<int NC>
__global__ void __launch_bounds__(256)
ey_k(const float* __restrict__ parts, const float* __restrict__ auxf,
     const float* __restrict__ svec, const float* __restrict__ bias,
     float* __restrict__ out)
{
    int i = blockIdx.x * 256 + threadIdx.x;
    int c = (i >> 9) & 255;
    float s = 0.f;
    #pragma unroll
    for (int q = 0; q < NC; q++) s += parts[(ll)q * BCL + i];
    out[i] = auxf[i] + svec[c] * (s + bias[c]);
}

// ---------------- merged G1+G2 kernel -----------------------------------------
__global__ void __launch_bounds__(256, 2)
g12_k(const hf* __restrict__ wa, const float* __restrict__ ba,
      const hf* __restrict__ wv, const float* __restrict__ bv,
      const hf* __restrict__ xb, hf* __restrict__ ag, hf* __restrict__ vvp)
{
    __shared__ __align__(16) hf As[3][128][32];
    __shared__ __align__(16) hf Bs[3][4096];
    int t = blockIdx.y;
    int b = blockIdx.z;
    const ll SB = (ll)NPn * Cn * Ln;
    const hf* Xz = xb + (ll)b * Cn * Ln;
    if (t < 12) {
        gemm_core<1, true, hf>(As, Bs, wa, ba, Xz, ag + (ll)b * SB, Cn, Cn,
                               t * 128, blockIdx.x * 128, nullptr, nullptr);
    } else {
        gemm_core<0, true, hf>(As, Bs, wv, bv, Xz, vvp + (ll)b * SB, Cn, Cn,
                               (t - 12) * 128, blockIdx.x * 128, nullptr, nullptr);
    }
}

// ---------------- fused off+ml mega-GEMM --------------------------------------
__global__ void __launch_bounds__(256, 2)
offml_k(const hf* __restrict__ woff, const hf* __restrict__ wm,
        const float* __restrict__ boff, const float* __restrict__ bm,
        const hf* __restrict__ ag, hf* __restrict__ offp, hf* __restrict__ mlp)
{
    __shared__ __align__(16) hf As[3][128][32];
    __shared__ __align__(16) hf Bs[3][4096];
    const int bnd[7]  = {0, 14, 32, 54, 80, 110, 144};
    const int preK[6] = {0, 7, 16, 27, 40, 55};
    int t = blockIdx.y;
    int b = blockIdx.z;
    int kind = (t >= 144) ? 1 : 0;
    int tt = t - kind * 144;
    int br = 0;
    #pragma unroll
    for (int j = 1; j < 6; j++) if (tt >= bnd[j]) br = j;
    int mloc = (tt - bnd[br]) * 128;
    int K = 7 + 2 * br;
    const hf*    W  = (kind ? wm : woff) + (ll)br * KMAXn * Cn * Cn + (ll)mloc * Cn;
    const float* bz = (kind ? bm : boff) + br * KMAXn * Cn + mloc;
    const hf*    Xz = ag + ((ll)b * NPn + br) * ((ll)Cn * Ln);
    hf* Y = (kind ? mlp : offp) + (ll)preK[br] * BCL
            + (ll)b * Cn * K * Ln + (ll)mloc * Ln;
    gemm_core<0, true, hf>(As, Bs, W, bz, Xz, Y, Cn, Cn, 0, blockIdx.x * 128,
                           nullptr, nullptr);
}

// ---------------- DCN (all branches, one launch) -------------------------------
template<int K>
__device__ __forceinline__ void dcn_body(
    const hf* __restrict__ off_all, const hf* __restrict__ ml_all,
    const hf* __restrict__ v_all, hf* __restrict__ dcn,
    int branch, ll regionBase)
{
    ll idx = (ll)blockIdx.x * 256 + threadIdx.x;
    int l = (int)(idx & (Ln - 1));
    int c = (int)((idx >> 9) & (Cn - 1));
    int b = (int)(idx >> 17);
    ll rowBase = regionBase + ((ll)b * Cn * K + (ll)c * K) * Ln + l;
    const hf* op = off_all + rowBase;
    const hf* mp = ml_all + rowBase;
    const hf* vp = v_all + ((ll)b * NPn + branch) * ((ll)Cn * Ln) + (ll)c * Ln;

    float mlv[K];
    float mx = -3.4e38f;
    #pragma unroll
    for (int k = 0; k < K; k++) { mlv[k] = __half2float(mp[(ll)k * Ln]); mx = fmaxf(mx, mlv[k]); }
    float s = 0.f;
    #pragma unroll
    for (int k = 0; k < K; k++) { mlv[k] = expf(mlv[k] - mx); s += mlv[k]; }
    float inv = 1.f / s;

    float acc = 0.f;
    #pragma unroll
    for (int k = 0; k < K; k++) {
        float p = (float)l + ((float)k - (float)(K - 1) * 0.5f) + __half2float(op[(ll)k * Ln]);
        float p0 = floorf(p);
        float w = p - p0;
        int i0 = (int)p0;
        float ga = (i0 >= 0 && i0 < Ln) ? __half2float(vp[i0]) : 0.f;
        float gb = (i0 + 1 >= 0 && i0 + 1 < Ln) ? __half2float(vp[i0 + 1]) : 0.f;
        acc += mlv[k] * ((1.f - w) * ga + w * gb);
    }
    dcn[((ll)b * NPn + branch) * ((ll)Cn * Ln) + (ll)c * Ln + l] = __float2half(acc * inv);
}

__global__ void __launch_bounds__(256)
dcnall_k(const hf* __restrict__ offp, const hf* __restrict__ mlp,
         const hf* __restrict__ vp, hf* __restrict__ dcnp)
{
    switch (blockIdx.y) {
        case 0: dcn_body<7 >(offp, mlp, vp, dcnp, 0, (ll)0 * BCL);  break;
        case 1: dcn_body<9 >(offp, mlp, vp, dcnp, 1, (ll)7 * BCL);  break;
        case 2: dcn_body<11>(offp, mlp, vp, dcnp, 2, (ll)16 * BCL); break;
        case 3: dcn_body<13>(offp, mlp, vp, dcnp, 3, (ll)27 * BCL); break;
        case 4: dcn_body<15>(offp, mlp, vp, dcnp, 4, (ll)40 * BCL); break;
        default: dcn_body<17>(offp, mlp, vp, dcnp, 5, (ll)55 * BCL); break;
    }
}

// ---------------- LayerNorm over C ------------------------------------------
__global__ void __launch_bounds__(256)
ln_k(const float* __restrict__ y, const float* __restrict__ g,
     const float* __restrict__ be, hf* __restrict__ tn)
{
    int l = blockIdx.x * 256 + threadIdx.x;
    int b = blockIdx.y;
    const float* yp = y + (ll)b * Cn * Ln + l;
    float s = 0.f, s2 = 0.f;
    #pragma unroll 8
    for (int c = 0; c < Cn; c++) {
        float v = yp[(ll)c * Ln];
        s += v; s2 += v * v;
    }
    float mu = s * (1.0f / Cn);
    float var = s2 * (1.0f / Cn) - mu * mu;
    float rstd = rsqrtf(var + 1e-6f);
    hf* tp = tn + (ll)b * Cn * Ln + l;
    #pragma unroll 8
    for (int c = 0; c < Cn; c++) {
        float v = yp[(ll)c * Ln];
        tp[(ll)c * Ln] = __float2half((v - mu) * rstd * g[c] + be[c]);
    }
}

// ----------------------------------------------------------------------------
extern "C" void kernel_launch(void* const* d_in, const int* in_sizes, int n_in,
                              void* d_out, int out_size)
{
    const float* x    = (const float*)d_in[0];
    const float* Wa   = (const float*)d_in[1];
    const float* ba   = (const float*)d_in[2];
    const float* Wvd  = (const float*)d_in[3];
    const float* bvd  = (const float*)d_in[4];
    const float* Woff = (const float*)d_in[5];
    const float* boff = (const float*)d_in[6];
    const float* Wm   = (const float*)d_in[7];
    const float* bm   = (const float*)d_in[8];
    const float* Wod  = (const float*)d_in[9];
    const float* bod  = (const float*)d_in[10];
    const float* Wv   = (const float*)d_in[11];
    const float* bv   = (const float*)d_in[12];
    const float* Wp   = (const float*)d_in[13];
    const float* bp   = (const float*)d_in[14];
    const float* ls   = (const float*)d_in[15];
    const float* g2   = (const float*)d_in[16];
    const float* lng  = (const float*)d_in[17];
    const float* lnb  = (const float*)d_in[18];
    const float* W1   = (const float*)d_in[19];
    const float* b1   = (const float*)d_in[20];
    const float* W2   = (const float*)d_in[21];
    const float* b2   = (const float*)d_in[22];
    float* out = (float*)d_out;

    hf *ag, *vvp, *vp, *dcnp, *prodp, *offp, *mlp, *tnp, *hp, *xb;
    hf *wa, *wvd, *wod, *wv, *wp, *woff, *wm, *w1, *w2;
    float *yp, *bps, *parts;
    cudaGetSymbolAddress((void**)&ag,    g_ag);
    cudaGetSymbolAddress((void**)&vvp,   g_vv);
    cudaGetSymbolAddress((void**)&vp,    g_v);
    cudaGetSymbolAddress((void**)&dcnp,  g_dcn);
    cudaGetSymbolAddress((void**)&prodp, g_prod);
    cudaGetSymbolAddress((void**)&offp,  g_off);
    cudaGetSymbolAddress((void**)&mlp,   g_ml);
    cudaGetSymbolAddress((void**)&yp,    g_y);
    cudaGetSymbolAddress((void**)&tnp,   g_tn);
    cudaGetSymbolAddress((void**)&hp,    g_h);
    cudaGetSymbolAddress((void**)&bps,   g_bps);
    cudaGetSymbolAddress((void**)&parts, g_part);
    cudaGetSymbolAddress((void**)&wa,    g_wa);
    cudaGetSymbolAddress((void**)&wvd,   g_wvd);
    cudaGetSymbolAddress((void**)&wod,   g_wod);
    cudaGetSymbolAddress((void**)&wv,    g_wv);
    cudaGetSymbolAddress((void**)&wp,    g_wp);
    cudaGetSymbolAddress((void**)&woff,  g_woff);
    cudaGetSymbolAddress((void**)&wm,    g_wm);
    cudaGetSymbolAddress((void**)&w1,    g_w1);
    cudaGetSymbolAddress((void**)&w2,    g_w2);
    cudaGetSymbolAddress((void**)&xb,    g_xb);

    // fused conversions (single launch)
    CvtArgs ca;
    const float* srcs[10] = {x, Wa, Wvd, Wod, Wv, Wp, Woff, Wm, W1, W2};
    hf* dsts[10] = {xb, wa, wvd, wod, wv, wp, woff, wm, w1, w2};
    int cnts[10] = {Bn*Cn*Ln, NPn*Cn*Cn, NPn*Cn*Cn, NPn*Cn*Cn, NPn*Cn*Cn, NPn*Cn*Cn,
                    NPn*KMAXn*Cn*Cn, NPn*KMAXn*Cn*Cn, HIDn*Cn, Cn*HIDn};
    ca.cum[0] = 0;
    for (int i = 0; i < 10; i++) {
        ca.src[i] = srcs[i]; ca.dst[i] = dsts[i];
        ca.cum[i + 1] = ca.cum[i] + cnts[i];
    }
    cvtall_k<<<8192, 256>>>(ca);
    bpsum_k<<<1, 256>>>(bp, bps);

    const ll SB = (ll)NPn * Cn * Ln;
    const ll SI = (ll)Cn * Ln;

    // G1+G2 merged: ag = gelu(Wa@x + ba); vv = Wv@x + bv   (f16 accum)
    g12_k<<<dim3(4, 24, Bn), 256>>>(wa, ba, wv, bv, xb, ag, vvp);
    // G3: v = Wvd[i]@ag_i + bvd[i]                  (f16 accum)
    gemm_t<0, true, hf><<<dim3(4, Cn / 128, NPn * Bn), 256>>>(
        wvd, bvd, ag, vp, Cn, Bn, (ll)Cn * Cn, Cn, SB, SI, SB, SI,
        nullptr, 0, 0, nullptr);
    // G4+G5 fused: off/ml projections                (f16 accum)
    offml_k<<<dim3(4, 288, Bn), 256>>>(woff, wm, boff, bm, ag, offp, mlp);
    // G6: DCN sampling
    dcnall_k<<<dim3((Bn * Cn * Ln) / 256, NPn), 256>>>(offp, mlp, vp, dcnp);
    // G7: prod = (Wod[i]@dcn_i + bod[i]) * vv_i      (f16 accum)
    gemm_t<2, true, hf><<<dim3(4, Cn / 128, NPn * Bn), 256>>>(
        wod, bod, dcnp, prodp, Cn, Bn, (ll)Cn * Cn, Cn, SB, SI, SB, SI,
        vvp, SB, SI, nullptr);
    // G8 split-K: 6 chunks of K=256 over branches -> partials, then epilogue
    gpart_k<<<dim3(4, 2, 6 * Bn), 256>>>(
        wp, Cn, (ll)Cn * Cn, prodp, SB, SI, parts);
    ey_k<6><<<(int)(BCL / 256), 256>>>(parts, x, ls, bps, yp);
    // G9: LayerNorm
    ln_k<<<dim3(Ln / 256, Bn), 256>>>(yp, lng, lnb, tnp);
    // G10: h = gelu(W1@tn + b1)                      (f16 accum)
    gemm_t<1, true, hf><<<dim3(4, HIDn / 128, Bn), 256>>>(
        w1, b1, tnp, hp, Cn, Bn, 0, 0, SI, 0, (ll)HIDn * Ln, 0,
        nullptr, 0, 0, nullptr);
    // G11 split-K: 4 chunks of K=256 over HID -> partials, then epilogue
    gpart_k<<<dim3(4, 2, 4 * Bn), 256>>>(
        w2, HIDn, (ll)256, hp, (ll)HIDn * Ln, (ll)256 * Ln, parts);
    ey_k<4><<<(int)(BCL / 256), 256>>>(parts, yp, g2, b2, out);
}

// round 15
// speedup vs baseline: 1.0917x; 1.0007x over previous
#include <cuda_runtime.h>
#include <cuda_fp16.h>
#include <cstdint>
#include <math.h>

#define Bn 8
#define Cn 256
#define Ln 512
#define NPn 6
#define KMAXn 17
#define HIDn 1024
#define SUMK 72
#define BCL ((ll)Bn*Cn*Ln)

typedef long long ll;
typedef __half hf;

// ---------------- scratch (device globals) ----------------------------------
__device__ __align__(16) hf g_ag  [(size_t)Bn*NPn*Cn*Ln];
__device__ __align__(16) hf g_vv  [(size_t)Bn*NPn*Cn*Ln];
__device__ __align__(16) hf g_v   [(size_t)Bn*NPn*Cn*Ln];
__device__ __align__(16) hf g_dcn [(size_t)Bn*NPn*Cn*Ln];
__device__ __align__(16) hf g_prod[(size_t)Bn*NPn*Cn*Ln];
__device__ __align__(16) hf g_off [(size_t)Bn*Cn*Ln*SUMK];
__device__ __align__(16) hf g_ml  [(size_t)Bn*Cn*Ln*SUMK];
__device__ __align__(16) float g_y [(size_t)Bn*Cn*Ln];
__device__ __align__(16) hf g_tn  [(size_t)Bn*Cn*Ln];
__device__ __align__(16) hf g_h   [(size_t)Bn*HIDn*Ln];
__device__ __align__(16) float g_part[(size_t)6*Bn*Cn*Ln];
__device__ float g_bps[Cn];
__device__ __align__(16) hf g_wa  [NPn*Cn*Cn];
__device__ __align__(16) hf g_wvd [NPn*Cn*Cn];
__device__ __align__(16) hf g_wod [NPn*Cn*Cn];
__device__ __align__(16) hf g_wv  [NPn*Cn*Cn];
__device__ __align__(16) hf g_wps [Cn*NPn*Cn];     // Wp stacked: [o][i*256+c]
__device__ __align__(16) hf g_woff[(size_t)NPn*KMAXn*Cn*Cn];
__device__ __align__(16) hf g_wm  [(size_t)NPn*KMAXn*Cn*Cn];
__device__ __align__(16) hf g_w1  [HIDn*Cn];
__device__ __align__(16) hf g_w2  [Cn*HIDn];
__device__ __align__(16) hf g_xb  [(size_t)Bn*Cn*Ln];

__device__ __forceinline__ float gelu_f(float v) {
    return 0.5f * v * (1.0f + erff(v * 0.7071067811865476f));
}

// ---------------- fused conversion --------------------------------------
struct CvtArgs {
    const float* src[9];
    hf* dst[9];
    int cum[10];
};
__global__ void __launch_bounds__(256)
cvtall_k(CvtArgs a)
{
    int total = a.cum[9];
    for (int i = blockIdx.x * 256 + threadIdx.x; i < total; i += gridDim.x * 256) {
        int s = 0;
        #pragma unroll
        for (int j = 1; j < 9; j++) if (i >= a.cum[j]) s = j;
        int off = i - a.cum[s];
        a.dst[s][off] = __float2half(a.src[s][off]);
    }
}

__global__ void __launch_bounds__(256)
wps_k(const float* __restrict__ Wp, hf* __restrict__ wps)
{
    int n = Cn * NPn * Cn;
    for (int j = blockIdx.x * 256 + threadIdx.x; j < n; j += gridDim.x * 256) {
        int o = j / (NPn * Cn), r = j % (NPn * Cn);
        int i = r >> 8, c = r & 255;
        wps[j] = __float2half(Wp[(ll)i * Cn * Cn + o * Cn + c]);
    }
}

__global__ void bpsum_k(const float* __restrict__ bp, float* __restrict__ out)
{
    int c = threadIdx.x;
    float s = 0.f;
    #pragma unroll
    for (int i = 0; i < NPn; i++) s += bp[i * Cn + c];
    out[c] = s;
}

// ---------------- asm wrappers ----------------------------------------------
__device__ __forceinline__ void cpa16u(uint32_t dst, const void* src) {
    asm volatile("cp.async.cg.shared.global [%0], [%1], 16;\n" :: "r"(dst), "l"(src));
}
__device__ __forceinline__ void ldsm4(uint32_t addr, uint32_t& r0, uint32_t& r1,
                                      uint32_t& r2, uint32_t& r3) {
    asm volatile("ldmatrix.sync.aligned.m8n8.x4.shared.b16 {%0,%1,%2,%3}, [%4];\n"
        : "=r"(r0), "=r"(r1), "=r"(r2), "=r"(r3) : "r"(addr));
}
__device__ __forceinline__ void ldsm4t(uint32_t addr, uint32_t& r0, uint32_t& r1,
                                       uint32_t& r2, uint32_t& r3) {
    asm volatile("ldmatrix.sync.aligned.m8n8.x4.trans.shared.b16 {%0,%1,%2,%3}, [%4];\n"
        : "=r"(r0), "=r"(r1), "=r"(r2), "=r"(r3) : "r"(addr));
}
__device__ __forceinline__ void mma_h32(float& d0, float& d1, float& d2, float& d3,
                                        uint32_t a0, uint32_t a1, uint32_t a2, uint32_t a3,
                                        uint32_t b0, uint32_t b1) {
    asm volatile(
        "mma.sync.aligned.m16n8k16.row.col.f32.f16.f16.f32 "
        "{%0,%1,%2,%3},{%4,%5,%6,%7},{%8,%9},{%0,%1,%2,%3};\n"
        : "+f"(d0), "+f"(d1), "+f"(d2), "+f"(d3)
        : "r"(a0), "r"(a1), "r"(a2), "r"(a3), "r"(b0), "r"(b1));
}
__device__ __forceinline__ void mma_h16(uint32_t& d0, uint32_t& d1,
                                        uint32_t a0, uint32_t a1, uint32_t a2, uint32_t a3,
                                        uint32_t b0, uint32_t b1) {
    asm volatile(
        "mma.sync.aligned.m16n8k16.row.col.f16.f16.f16.f16 "
        "{%0,%1},{%2,%3,%4,%5},{%6,%7},{%0,%1};\n"
        : "+r"(d0), "+r"(d1)
        : "r"(a0), "r"(a1), "r"(a2), "r"(a3), "r"(b0), "r"(b1));
}

// ---------------- GEMM core (128x128 CTA, 8 warps, warp tile 32x64) ----------
// EPI: 0 none, 1 gelu, 2 *aux(hf), 3 aux(f32)+svec*(.), 5 raw f32 store (no bias)
template<int EPI, bool ACC16, typename OutT>
__device__ __forceinline__ void gemm_core(
    hf (*As)[128][32], hf (*Bs)[4096],
    const hf* __restrict__ Wz, const float* __restrict__ bz,
    const hf* __restrict__ Xz, OutT* __restrict__ Yz,
    int KDIM, int wLD, int m0, int n0,
    const void* __restrict__ aux, const float* __restrict__ svec)
{
    const int tid = threadIdx.x, lane = tid & 31, wid = tid >> 5;
    const int wm = wid >> 1, wn = wid & 1;

    float acc[ACC16 ? 1 : 2][8][4];
    uint32_t acch[ACC16 ? 2 : 1][8][2];
    if (!ACC16) {
        #pragma unroll
        for (int i = 0; i < (ACC16 ? 1 : 2); i++)
            #pragma unroll
            for (int j = 0; j < 8; j++)
                #pragma unroll
                for (int q = 0; q < 4; q++) acc[i][j][q] = 0.f;
    } else {
        #pragma unroll
        for (int i = 0; i < (ACC16 ? 2 : 1); i++)
            #pragma unroll
            for (int j = 0; j < 8; j++) { acch[i][j][0] = 0u; acch[i][j][1] = 0u; }
    }

    const uint32_t asBase = (uint32_t)__cvta_generic_to_shared(&As[0][0][0]);
    const uint32_t bBase  = (uint32_t)__cvta_generic_to_shared(&Bs[0][0]);

    const int mA = tid >> 2, cA = tid & 3;
    const int kB = tid >> 4, nB = tid & 15;
    const hf* srcA0 = Wz + (ll)(m0 + mA) * wLD + cA * 8;
    const hf* srcA1 = Wz + (ll)(m0 + mA + 64) * wLD + cA * 8;
    const hf* srcB0 = Xz + (ll)kB * Ln + n0 + nB * 8;
    const hf* srcB1 = Xz + (ll)(kB + 16) * Ln + n0 + nB * 8;
    const uint32_t dA0 = asBase + (uint32_t)(mA * 64 + (cA ^ ((mA >> 1) & 3)) * 16);
    const uint32_t dA1 = asBase + (uint32_t)((mA + 64) * 64 + (cA ^ (((mA + 64) >> 1) & 3)) * 16);
    const uint32_t dB0 = bBase + (uint32_t)((kB * 16 + (nB ^ (kB & 7))) * 16);
    const uint32_t dB1 = bBase + (uint32_t)(((kB + 16) * 16 + (nB ^ ((kB + 16) & 7))) * 16);

    auto loadStage = [&](uint32_t so) {
        cpa16u(dA0 + so, srcA0);
        cpa16u(dA1 + so, srcA1);
        cpa16u(dB0 + so, srcB0);
        cpa16u(dB1 + so, srcB1);
        srcB0 += 32 * Ln; srcB1 += 32 * Ln;
        srcA0 += 32; srcA1 += 32;
    };

    uint32_t aAddr[2][2], bAddr[4];
    #pragma unroll
    for (int mt = 0; mt < 2; mt++)
        #pragma unroll
        for (int ks = 0; ks < 2; ks++) {
            int rowp = wm * 32 + mt * 16 + (lane & 15);
            int physA = ((ks * 2) + (lane >> 4)) ^ ((rowp >> 1) & 3);
            aAddr[mt][ks] = asBase + (uint32_t)(rowp * 64 + physA * 16);
        }
    #pragma unroll
    for (int pr = 0; pr < 4; pr++) {
        int phys = (wn * 8 + pr * 2 + (lane >> 4)) ^ (lane & 7);
        bAddr[pr] = bBase + (uint32_t)((lane & 15) * 256 + phys * 16);
    }

    const int nIt = KDIM >> 5;
    loadStage(0);
    asm volatile("cp.async.commit_group;\n");
    loadStage(8192);
    asm volatile("cp.async.commit_group;\n");

    uint32_t ldSlot = 16384, sOff = 0;
    for (int it = 0; it < nIt; it++) {
        if (it + 1 < nIt) asm volatile("cp.async.wait_group 1;\n");
        else              asm volatile("cp.async.wait_group 0;\n");
        __syncthreads();
        if (it + 2 < nIt) {
            loadStage(ldSlot);
            ldSlot = (ldSlot == 16384) ? 0 : ldSlot + 8192;
        }
        asm volatile("cp.async.commit_group;\n");

        #pragma unroll
        for (int ks = 0; ks < 2; ks++) {
            uint32_t fa[2][4];
            {
                uint32_t t0, t1, t2, t3;
                ldsm4(aAddr[0][ks] + sOff, t0, t1, t2, t3);
                fa[0][0] = t0; fa[0][1] = t1; fa[0][2] = t2; fa[0][3] = t3;
                ldsm4(aAddr[1][ks] + sOff, t0, t1, t2, t3);
                fa[1][0] = t0; fa[1][1] = t1; fa[1][2] = t2; fa[1][3] = t3;
            }
            uint32_t fb[4][4];
            #pragma unroll
            for (int pr = 0; pr < 4; pr++) {
                uint32_t t0, t1, t2, t3;
                ldsm4t(bAddr[pr] + (uint32_t)(ks * 4096) + sOff, t0, t1, t2, t3);
                fb[pr][0] = t0; fb[pr][1] = t1; fb[pr][2] = t2; fb[pr][3] = t3;
            }
            #pragma unroll
            for (int mt = 0; mt < 2; mt++)
                #pragma unroll
                for (int nt = 0; nt < 8; nt++) {
                    if (ACC16) {
                        uint32_t c0 = acch[mt][nt][0], c1 = acch[mt][nt][1];
                        mma_h16(c0, c1,
                                fa[mt][0], fa[mt][1], fa[mt][2], fa[mt][3],
                                fb[nt >> 1][(nt & 1) * 2], fb[nt >> 1][(nt & 1) * 2 + 1]);
                        acch[mt][nt][0] = c0; acch[mt][nt][1] = c1;
                    } else {
                        float c0 = acc[mt][nt][0], c1 = acc[mt][nt][1];
                        float c2 = acc[mt][nt][2], c3 = acc[mt][nt][3];
                        mma_h32(c0, c1, c2, c3,
                                fa[mt][0], fa[mt][1], fa[mt][2], fa[mt][3],
                                fb[nt >> 1][(nt & 1) * 2], fb[nt >> 1][(nt & 1) * 2 + 1]);
                        acc[mt][nt][0] = c0; acc[mt][nt][1] = c1;
                        acc[mt][nt][2] = c2; acc[mt][nt][3] = c3;
                    }
                }
        }
        sOff = (sOff == 16384) ? 0 : sOff + 8192;
    }

    // epilogue
    const int row = lane >> 2, colp = (lane & 3) * 2;
    #pragma unroll
    for (int mt = 0; mt < 2; mt++) {
        #pragma unroll
        for (int h = 0; h < 2; h++) {
            int o = m0 + wm * 32 + mt * 16 + row + h * 8;
            float bb = (EPI == 5) ? 0.f : bz[o];
            float sv = (EPI == 3) ? svec[o] : 0.f;
            #pragma unroll
            for (int nt = 0; nt < 8; nt++) {
                int l = n0 + wn * 64 + nt * 8 + colp;
                ll yi = (ll)o * Ln + l;
                float r0, r1;
                if (ACC16) {
                    __half2 hv = *(__half2*)&acch[mt][nt][h];
                    r0 = __low2float(hv) + bb;
                    r1 = __high2float(hv) + bb;
                } else {
                    r0 = acc[mt][nt][h * 2 + 0] + bb;
                    r1 = acc[mt][nt][h * 2 + 1] + bb;
                }
                if (EPI == 1) { r0 = gelu_f(r0); r1 = gelu_f(r1); }
                if (EPI == 2) {
                    __half2 av = *(const __half2*)(((const hf*)aux) + yi);
                    r0 *= __low2float(av); r1 *= __high2float(av);
                }
                if (EPI == 3) {
                    float2 av = *(const float2*)(((const float*)aux) + yi);
                    r0 = av.x + sv * r0; r1 = av.y + sv * r1;
                }
                if (sizeof(OutT) == 2) {
                    __half2 pv = __floats2half2_rn(r0, r1);
                    *(__half2*)((hf*)Yz + yi) = pv;
                } else {
                    float2 fv; fv.x = r0; fv.y = r1;
                    *(float2*)((float*)Yz + yi) = fv;
                }
            }
        }
    }
}

// ---------------- generic GEMM kernel wrapper --------------------------------
template<int EPI, bool ACC16, typename OutT>
__global__ void __launch_bounds__(256, 2)
gemm_t(const hf* __restrict__ W, const float* __restrict__ bias,
       const hf* __restrict__ X, OutT* __restrict__ Y,
       int KDIM, int zB,
       ll wStrideI, int bStrideI,
       ll xStrideB, ll xStrideI,
       ll yStrideB, ll yStrideI,
       const void* __restrict__ aux, ll aStrideB, ll aStrideI,
       const float* __restrict__ svec)
{
    __shared__ __align__(16) hf As[3][128][32];
    __shared__ __align__(16) hf Bs[3][4096];
    const int z = blockIdx.z;
    const int b = z % zB, br = z / zB;
    const hf*  Wz = W + (ll)br * wStrideI;
    const float* bz = bias + (ll)br * bStrideI;
    const hf*  Xz = X + (ll)b * xStrideB + (ll)br * xStrideI;
    OutT* Yz = Y + (ll)b * yStrideB + (ll)br * yStrideI;
    const void* auxp = nullptr;
    if (EPI == 2) auxp = ((const hf*)aux) + (ll)b * aStrideB + (ll)br * aStrideI;
    if (EPI == 3) auxp = ((const float*)aux) + (ll)b * aStrideB + (ll)br * aStrideI;
    gemm_core<EPI, ACC16, OutT>(As, Bs, Wz, bz, Xz, Yz, KDIM, KDIM,
                                blockIdx.y * 128, blockIdx.x * 128, auxp, svec);
}

// ---------------- split-K partial GEMM ---------------------------------------
__global__ void __launch_bounds__(256, 2)
gpart_k(const hf* __restrict__ W, int wLD, ll wChunk,
        const hf* __restrict__ X, ll xStrideB, ll xChunk,
        float* __restrict__ parts, int KDIM, int nCh)
{
    __shared__ __align__(16) hf As[3][128][32];
    __shared__ __align__(16) hf Bs[3][4096];
    int z = blockIdx.z;
    int b = z % Bn, ch = z / Bn;
    const hf* Wz = W + (ll)ch * wChunk;
    const hf* Xz = X + (ll)b * xStrideB + (ll)ch * xChunk;
    float* Yz = parts + (ll)ch * BCL + (ll)b * Cn * Ln;
    gemm_core<5, false, float>(As, Bs, Wz, nullptr, Xz, Yz, KDIM, wLD,
                               blockIdx.y * 128, blockIdx.x * 128, nullptr, nullptr);
}

// ---------------- split-K epilogue: out = aux + svec*(sum(parts) + bias) ------
template<int NC>
__global__ void __launch_bounds__(256)
ey_k(const float* __restrict__ parts, const float* __restrict__ auxf,
     const float* __restrict__ svec, const float* __restrict__ bias,
     float* __restrict__ out)
{
    int i = blockIdx.x * 256 + threadIdx.x;
    int c = (i >> 9) & 255;
    float s = 0.f;
    #pragma unroll
    for (int q = 0; q < NC; q++) s += parts[(ll)q * BCL + i];
    out[i] = auxf[i] + svec[c] * (s + bias[c]);
}

// ---------------- merged G1+G2 kernel -----------------------------------------
__global__ void __launch_bounds__(256, 2)
g12_k(const hf* __restrict__ wa, const float* __restrict__ ba,
      const hf* __restrict__ wv, const float* __restrict__ bv,
      const hf* __restrict__ xb, hf* __restrict__ ag, hf* __restrict__ vvp)
{
    __shared__ __align__(16) hf As[3][128][32];
    __shared__ __align__(16) hf Bs[3][4096];
    int t = blockIdx.y;
    int b = blockIdx.z;
    const ll SB = (ll)NPn * Cn * Ln;
    const hf* Xz = xb + (ll)b * Cn * Ln;
    if (t < 12) {
        gemm_core<1, true, hf>(As, Bs, wa, ba, Xz, ag + (ll)b * SB, Cn, Cn,
                               t * 128, blockIdx.x * 128, nullptr, nullptr);
    } else {
        gemm_core<0, true, hf>(As, Bs, wv, bv, Xz, vvp + (ll)b * SB, Cn, Cn,
                               (t - 12) * 128, blockIdx.x * 128, nullptr, nullptr);
    }
}

// ---------------- fused off+ml+G3 mega-GEMM -----------------------------------
__global__ void __launch_bounds__(256, 2)
offml_k(const hf* __restrict__ woff, const hf* __restrict__ wm,
        const float* __restrict__ boff, const float* __restrict__ bm,
        const hf* __restrict__ wvd, const float* __restrict__ bvd,
        const hf* __restrict__ ag, hf* __restrict__ offp, hf* __restrict__ mlp,
        hf* __restrict__ vp)
{
    __shared__ __align__(16) hf As[3][128][32];
    __shared__ __align__(16) hf Bs[3][4096];
    const int bnd[7]  = {0, 14, 32, 54, 80, 110, 144};
    const int preK[6] = {0, 7, 16, 27, 40, 55};
    int t = blockIdx.y;
    int b = blockIdx.z;
    const ll SI = (ll)Cn * Ln;
    if (t >= 288) {
        // G3 tiles: v = Wvd[br]@ag_br + bvd[br]
        int t2 = t - 288;             // 0..11
        int br = t2 >> 1, mt = t2 & 1;
        const hf* Xz = ag + ((ll)b * NPn + br) * SI;
        gemm_core<0, true, hf>(As, Bs, wvd + (ll)br * Cn * Cn, bvd + br * Cn,
                               Xz, vp + ((ll)b * NPn + br) * SI, Cn, Cn,
                               mt * 128, blockIdx.x * 128, nullptr, nullptr);
        return;
    }
    int kind = (t >= 144) ? 1 : 0;
    int tt = t - kind * 144;
    int br = 0;
    #pragma unroll
    for (int j = 1; j < 6; j++) if (tt >= bnd[j]) br = j;
    int mloc = (tt - bnd[br]) * 128;
    int K = 7 + 2 * br;
    const hf*    W  = (kind ? wm : woff) + (ll)br * KMAXn * Cn * Cn + (ll)mloc * Cn;
    const float* bz = (kind ? bm : boff) + br * KMAXn * Cn + mloc;
    const hf*    Xz = ag + ((ll)b * NPn + br) * SI;
    hf* Y = (kind ? mlp : offp) + (ll)preK[br] * BCL
            + (ll)b * Cn * K * Ln + (ll)mloc * Ln;
    gemm_core<0, true, hf>(As, Bs, W, bz, Xz, Y, Cn, Cn, 0, blockIdx.x * 128,
                           nullptr, nullptr);
}

// ---------------- DCN (all branches, one launch) -------------------------------
template<int K>
__device__ __forceinline__ void dcn_body(
    const hf* __restrict__ off_all, const hf* __restrict__ ml_all,
    const hf* __restrict__ v_all, hf* __restrict__ dcn,
    int branch, ll regionBase)
{
    ll idx = (ll)blockIdx.x * 256 + threadIdx.x;
    int l = (int)(idx & (Ln - 1));
    int c = (int)((idx >> 9) & (Cn - 1));
    int b = (int)(idx >> 17);
    ll rowBase = regionBase + ((ll)b * Cn * K + (ll)c * K) * Ln + l;
    const hf* op = off_all + rowBase;
    const hf* mp = ml_all + rowBase;
    const hf* vp = v_all + ((ll)b * NPn + branch) * ((ll)Cn * Ln) + (ll)c * Ln;

    float mlv[K];
    float mx = -3.4e38f;
    #pragma unroll
    for (int k = 0; k < K; k++) { mlv[k] = __half2float(mp[(ll)k * Ln]); mx = fmaxf(mx, mlv[k]); }
    float s = 0.f;
    #pragma unroll
    for (int k = 0; k < K; k++) { mlv[k] = expf(mlv[k] - mx); s += mlv[k]; }
    float inv = 1.f / s;

    float acc = 0.f;
    #pragma unroll
    for (int k = 0; k < K; k++) {
        float p = (float)l + ((float)k - (float)(K - 1) * 0.5f) + __half2float(op[(ll)k * Ln]);
        float p0 = floorf(p);
        float w = p - p0;
        int i0 = (int)p0;
        float ga = (i0 >= 0 && i0 < Ln) ? __half2float(vp[i0]) : 0.f;
        float gb = (i0 + 1 >= 0 && i0 + 1 < Ln) ? __half2float(vp[i0 + 1]) : 0.f;
        acc += mlv[k] * ((1.f - w) * ga + w * gb);
    }
    dcn[((ll)b * NPn + branch) * ((ll)Cn * Ln) + (ll)c * Ln + l] = __float2half(acc * inv);
}

__global__ void __launch_bounds__(256)
dcnall_k(const hf* __restrict__ offp, const hf* __restrict__ mlp,
         const hf* __restrict__ vp, hf* __restrict__ dcnp)
{
    switch (blockIdx.y) {
        case 0: dcn_body<7 >(offp, mlp, vp, dcnp, 0, (ll)0 * BCL);  break;
        case 1: dcn_body<9 >(offp, mlp, vp, dcnp, 1, (ll)7 * BCL);  break;
        case 2: dcn_body<11>(offp, mlp, vp, dcnp, 2, (ll)16 * BCL); break;
        case 3: dcn_body<13>(offp, mlp, vp, dcnp, 3, (ll)27 * BCL); break;
        case 4: dcn_body<15>(offp, mlp, vp, dcnp, 4, (ll)40 * BCL); break;
        default: dcn_body<17>(offp, mlp, vp, dcnp, 5, (ll)55 * BCL); break;
    }
}

// ---------------- LayerNorm over C ------------------------------------------
__global__ void __launch_bounds__(256)
ln_k(const float* __restrict__ y, const float* __restrict__ g,
     const float* __restrict__ be, hf* __restrict__ tn)
{
    int l = blockIdx.x * 256 + threadIdx.x;
    int b = blockIdx.y;
    const float* yp = y + (ll)b * Cn * Ln + l;
    float s = 0.f, s2 = 0.f;
    #pragma unroll 8
    for (int c = 0; c < Cn; c++) {
        float v = yp[(ll)c * Ln];
        s += v; s2 += v * v;
    }
    float mu = s * (1.0f / Cn);
    float var = s2 * (1.0f / Cn) - mu * mu;
    float rstd = rsqrtf(var + 1e-6f);
    hf* tp = tn + (ll)b * Cn * Ln + l;
    #pragma unroll 8
    for (int c = 0; c < Cn; c++) {
        float v = yp[(ll)c * Ln];
        tp[(ll)c * Ln] = __float2half((v - mu) * rstd * g[c] + be[c]);
    }
}

// ----------------------------------------------------------------------------
extern "C" void kernel_launch(void* const* d_in, const int* in_sizes, int n_in,
                              void* d_out, int out_size)
{
    const float* x    = (const float*)d_in[0];
    const float* Wa   = (const float*)d_in[1];
    const float* ba   = (const float*)d_in[2];
    const float* Wvd  = (const float*)d_in[3];
    const float* bvd  = (const float*)d_in[4];
    const float* Woff = (const float*)d_in[5];
    const float* boff = (const float*)d_in[6];
    const float* Wm   = (const float*)d_in[7];
    const float* bm   = (const float*)d_in[8];
    const float* Wod  = (const float*)d_in[9];
    const float* bod  = (const float*)d_in[10];
    const float* Wv   = (const float*)d_in[11];
    const float* bv   = (const float*)d_in[12];
    const float* Wp   = (const float*)d_in[13];
    const float* bp   = (const float*)d_in[14];
    const float* ls   = (const float*)d_in[15];
    const float* g2   = (const float*)d_in[16];
    const float* lng  = (const float*)d_in[17];
    const float* lnb  = (const float*)d_in[18];
    const float* W1   = (const float*)d_in[19];
    const float* b1   = (const float*)d_in[20];
    const float* W2   = (const float*)d_in[21];
    const float* b2   = (const float*)d_in[22];
    float* out = (float*)d_out;

    hf *ag, *vvp, *vp, *dcnp, *prodp, *offp, *mlp, *tnp, *hp, *xb;
    hf *wa, *wvd, *wod, *wv, *wps, *woff, *wm, *w1, *w2;
    float *yp, *bps, *parts;
    cudaGetSymbolAddress((void**)&ag,    g_ag);
    cudaGetSymbolAddress((void**)&vvp,   g_vv);
    cudaGetSymbolAddress((void**)&vp,    g_v);
    cudaGetSymbolAddress((void**)&dcnp,  g_dcn);
    cudaGetSymbolAddress((void**)&prodp, g_prod);
    cudaGetSymbolAddress((void**)&offp,  g_off);
    cudaGetSymbolAddress((void**)&mlp,   g_ml);
    cudaGetSymbolAddress((void**)&yp,    g_y);
    cudaGetSymbolAddress((void**)&tnp,   g_tn);
    cudaGetSymbolAddress((void**)&hp,    g_h);
    cudaGetSymbolAddress((void**)&bps,   g_bps);
    cudaGetSymbolAddress((void**)&parts, g_part);
    cudaGetSymbolAddress((void**)&wa,    g_wa);
    cudaGetSymbolAddress((void**)&wvd,   g_wvd);
    cudaGetSymbolAddress((void**)&wod,   g_wod);
    cudaGetSymbolAddress((void**)&wv,    g_wv);
    cudaGetSymbolAddress((void**)&wps,   g_wps);
    cudaGetSymbolAddress((void**)&woff,  g_woff);
    cudaGetSymbolAddress((void**)&wm,    g_wm);
    cudaGetSymbolAddress((void**)&w1,    g_w1);
    cudaGetSymbolAddress((void**)&w2,    g_w2);
    cudaGetSymbolAddress((void**)&xb,    g_xb);

    // fused conversions (single launch) + Wp permute + bias sum
    CvtArgs ca;
    const float* srcs[9] = {x, Wa, Wvd, Wod, Wv, Woff, Wm, W1, W2};
    hf* dsts[9] = {xb, wa, wvd, wod, wv, woff, wm, w1, w2};
    int cnts[9] = {Bn*Cn*Ln, NPn*Cn*Cn, NPn*Cn*Cn, NPn*Cn*Cn, NPn*Cn*Cn,
                   NPn*KMAXn*Cn*Cn, NPn*KMAXn*Cn*Cn, HIDn*Cn, Cn*HIDn};
    ca.cum[0] = 0;
    for (int i = 0; i < 9; i++) {
        ca.src[i] = srcs[i]; ca.dst[i] = dsts[i];
        ca.cum[i + 1] = ca.cum[i] + cnts[i];
    }
    cvtall_k<<<8192, 256>>>(ca);
    wps_k<<<1536, 256>>>(Wp, wps);
    bpsum_k<<<1, 256>>>(bp, bps);

    const ll SB = (ll)NPn * Cn * Ln;
    const ll SI = (ll)Cn * Ln;

    // G1+G2 merged: ag = gelu(Wa@x + ba); vv = Wv@x + bv   (f16 accum)
    g12_k<<<dim3(4, 24, Bn), 256>>>(wa, ba, wv, bv, xb, ag, vvp);
    // G4+G5+G3 mega-grid: off/ml projections + v = Wvd@ag   (f16 accum)
    offml_k<<<dim3(4, 300, Bn), 256>>>(woff, wm, boff, bm, wvd, bvd,
                                       ag, offp, mlp, vp);
    // G6: DCN sampling
    dcnall_k<<<dim3((Bn * Cn * Ln) / 256, NPn), 256>>>(offp, mlp, vp, dcnp);
    // G7: prod = (Wod[i]@dcn_i + bod[i]) * vv_i      (f16 accum)
    gemm_t<2, true, hf><<<dim3(4, Cn / 128, NPn * Bn), 256>>>(
        wod, bod, dcnp, prodp, Cn, Bn, (ll)Cn * Cn, Cn, SB, SI, SB, SI,
        vvp, SB, SI, nullptr);
    // G8 split-K: 4 chunks of K=384 over stacked Wp -> partials, then epilogue
    gpart_k<<<dim3(4, 2, 4 * Bn), 256>>>(
        wps, NPn * Cn, (ll)384, prodp, SB, (ll)384 * Ln, parts, 384, 4);
    ey_k<4><<<(int)(BCL / 256), 256>>>(parts, x, ls, bps, yp);
    // G9: LayerNorm
    ln_k<<<dim3(Ln / 256, Bn), 256>>>(yp, lng, lnb, tnp);
    // G10: h = gelu(W1@tn + b1)                      (f16 accum)
    gemm_t<1, true, hf><<<dim3(4, HIDn / 128, Bn), 256>>>(
        w1, b1, tnp, hp, Cn, Bn, 0, 0, SI, 0, (ll)HIDn * Ln, 0,
        nullptr, 0, 0, nullptr);
    // G11 split-K: 4 chunks of K=256 over HID -> partials, then epilogue
    gpart_k<<<dim3(4, 2, 4 * Bn), 256>>>(
        w2, HIDn, (ll)256, hp, (ll)HIDn * Ln, (ll)256 * Ln, parts, 256, 4);
    ey_k<4><<<(int)(BCL / 256), 256>>>(parts, yp, g2, b2, out);
}

// round 16
// speedup vs baseline: 1.1280x; 1.0332x over previous
#include <cuda_runtime.h>
#include <cuda_fp16.h>
#include <cstdint>
#include <math.h>

#define Bn 8
#define Cn 256
#define Ln 512
#define NPn 6
#define KMAXn 17
#define HIDn 1024
#define SUMK 72
#define BCL ((ll)Bn*Cn*Ln)

typedef long long ll;
typedef __half hf;

// ---------------- scratch (device globals) ----------------------------------
__device__ __align__(16) hf g_ag  [(size_t)Bn*NPn*Cn*Ln];
__device__ __align__(16) hf g_vv  [(size_t)Bn*NPn*Cn*Ln];
__device__ __align__(16) hf g_v   [(size_t)Bn*NPn*Cn*Ln];
__device__ __align__(16) hf g_dcn [(size_t)Bn*NPn*Cn*Ln];
__device__ __align__(16) hf g_prod[(size_t)Bn*NPn*Cn*Ln];
__device__ __align__(16) hf g_off [(size_t)Bn*Cn*Ln*SUMK];
__device__ __align__(16) hf g_ml  [(size_t)Bn*Cn*Ln*SUMK];
__device__ __align__(16) float g_y [(size_t)Bn*Cn*Ln];
__device__ __align__(16) hf g_tn  [(size_t)Bn*Cn*Ln];
__device__ __align__(16) hf g_h   [(size_t)Bn*HIDn*Ln];
__device__ __align__(16) float g_part[(size_t)6*Bn*Cn*Ln];
__device__ float g_bps[Cn];
__device__ __align__(16) hf g_wa  [NPn*Cn*Cn];
__device__ __align__(16) hf g_wvd [NPn*Cn*Cn];
__device__ __align__(16) hf g_wod [NPn*Cn*Cn];
__device__ __align__(16) hf g_wv  [NPn*Cn*Cn];
__device__ __align__(16) hf g_wps [Cn*NPn*Cn];     // Wp stacked: [o][i*256+c]
__device__ __align__(16) hf g_woff[(size_t)NPn*KMAXn*Cn*Cn];
__device__ __align__(16) hf g_wm  [(size_t)NPn*KMAXn*Cn*Cn];
__device__ __align__(16) hf g_w1  [HIDn*Cn];
__device__ __align__(16) hf g_w2  [Cn*HIDn];
__device__ __align__(16) hf g_xb  [(size_t)Bn*Cn*Ln];

__device__ __forceinline__ float gelu_f(float v) {
    return 0.5f * v * (1.0f + erff(v * 0.7071067811865476f));
}

// ---------------- fused conversion --------------------------------------
struct CvtArgs {
    const float* src[9];
    hf* dst[9];
    int cum[10];
};
__global__ void __launch_bounds__(256)
cvtall_k(CvtArgs a)
{
    int total = a.cum[9];
    for (int i = blockIdx.x * 256 + threadIdx.x; i < total; i += gridDim.x * 256) {
        int s = 0;
        #pragma unroll
        for (int j = 1; j < 9; j++) if (i >= a.cum[j]) s = j;
        int off = i - a.cum[s];
        a.dst[s][off] = __float2half(a.src[s][off]);
    }
}

__global__ void __launch_bounds__(256)
wps_k(const float* __restrict__ Wp, hf* __restrict__ wps)
{
    int n = Cn * NPn * Cn;
    for (int j = blockIdx.x * 256 + threadIdx.x; j < n; j += gridDim.x * 256) {
        int o = j / (NPn * Cn), r = j % (NPn * Cn);
        int i = r >> 8, c = r & 255;
        wps[j] = __float2half(Wp[(ll)i * Cn * Cn + o * Cn + c]);
    }
}

__global__ void bpsum_k(const float* __restrict__ bp, float* __restrict__ out)
{
    int c = threadIdx.x;
    float s = 0.f;
    #pragma unroll
    for (int i = 0; i < NPn; i++) s += bp[i * Cn + c];
    out[c] = s;
}

// ---------------- asm wrappers ----------------------------------------------
__device__ __forceinline__ void cpa16u(uint32_t dst, const void* src) {
    asm volatile("cp.async.cg.shared.global [%0], [%1], 16;\n" :: "r"(dst), "l"(src));
}
__device__ __forceinline__ void ldsm4(uint32_t addr, uint32_t& r0, uint32_t& r1,
                                      uint32_t& r2, uint32_t& r3) {
    asm volatile("ldmatrix.sync.aligned.m8n8.x4.shared.b16 {%0,%1,%2,%3}, [%4];\n"
        : "=r"(r0), "=r"(r1), "=r"(r2), "=r"(r3) : "r"(addr));
}
__device__ __forceinline__ void ldsm4t(uint32_t addr, uint32_t& r0, uint32_t& r1,
                                       uint32_t& r2, uint32_t& r3) {
    asm volatile("ldmatrix.sync.aligned.m8n8.x4.trans.shared.b16 {%0,%1,%2,%3}, [%4];\n"
        : "=r"(r0), "=r"(r1), "=r"(r2), "=r"(r3) : "r"(addr));
}
__device__ __forceinline__ void mma_h32(float& d0, float& d1, float& d2, float& d3,
                                        uint32_t a0, uint32_t a1, uint32_t a2, uint32_t a3,
                                        uint32_t b0, uint32_t b1) {
    asm volatile(
        "mma.sync.aligned.m16n8k16.row.col.f32.f16.f16.f32 "
        "{%0,%1,%2,%3},{%4,%5,%6,%7},{%8,%9},{%0,%1,%2,%3};\n"
        : "+f"(d0), "+f"(d1), "+f"(d2), "+f"(d3)
        : "r"(a0), "r"(a1), "r"(a2), "r"(a3), "r"(b0), "r"(b1));
}
__device__ __forceinline__ void mma_h16(uint32_t& d0, uint32_t& d1,
                                        uint32_t a0, uint32_t a1, uint32_t a2, uint32_t a3,
                                        uint32_t b0, uint32_t b1) {
    asm volatile(
        "mma.sync.aligned.m16n8k16.row.col.f16.f16.f16.f16 "
        "{%0,%1},{%2,%3,%4,%5},{%6,%7},{%0,%1};\n"
        : "+r"(d0), "+r"(d1)
        : "r"(a0), "r"(a1), "r"(a2), "r"(a3), "r"(b0), "r"(b1));
}

// ---------------- GEMM core (128x128 CTA, 8 warps, warp tile 32x64) ----------
// EPI: 0 none, 1 gelu, 2 *aux(hf), 3 aux(f32)+svec*(.), 5 raw f32 store (no bias)
template<int EPI, bool ACC16, typename OutT>
__device__ __forceinline__ void gemm_core(
    hf (*As)[128][32], hf (*Bs)[4096],
    const hf* __restrict__ Wz, const float* __restrict__ bz,
    const hf* __restrict__ Xz, OutT* __restrict__ Yz,
    int KDIM, int wLD, int m0, int n0,
    const void* __restrict__ aux, const float* __restrict__ svec)
{
    const int tid = threadIdx.x, lane = tid & 31, wid = tid >> 5;
    const int wm = wid >> 1, wn = wid & 1;

    float acc[ACC16 ? 1 : 2][8][4];
    uint32_t acch[ACC16 ? 2 : 1][8][2];
    if (!ACC16) {
        #pragma unroll
        for (int i = 0; i < (ACC16 ? 1 : 2); i++)
            #pragma unroll
            for (int j = 0; j < 8; j++)
                #pragma unroll
                for (int q = 0; q < 4; q++) acc[i][j][q] = 0.f;
    } else {
        #pragma unroll
        for (int i = 0; i < (ACC16 ? 2 : 1); i++)
            #pragma unroll
            for (int j = 0; j < 8; j++) { acch[i][j][0] = 0u; acch[i][j][1] = 0u; }
    }

    const uint32_t asBase = (uint32_t)__cvta_generic_to_shared(&As[0][0][0]);
    const uint32_t bBase  = (uint32_t)__cvta_generic_to_shared(&Bs[0][0]);

    const int mA = tid >> 2, cA = tid & 3;
    const int kB = tid >> 4, nB = tid & 15;
    const hf* srcA0 = Wz + (ll)(m0 + mA) * wLD + cA * 8;
    const hf* srcA1 = Wz + (ll)(m0 + mA + 64) * wLD + cA * 8;
    const hf* srcB0 = Xz + (ll)kB * Ln + n0 + nB * 8;
    const hf* srcB1 = Xz + (ll)(kB + 16) * Ln + n0 + nB * 8;
    const uint32_t dA0 = asBase + (uint32_t)(mA * 64 + (cA ^ ((mA >> 1) & 3)) * 16);
    const uint32_t dA1 = asBase + (uint32_t)((mA + 64) * 64 + (cA ^ (((mA + 64) >> 1) & 3)) * 16);
    const uint32_t dB0 = bBase + (uint32_t)((kB * 16 + (nB ^ (kB & 7))) * 16);
    const uint32_t dB1 = bBase + (uint32_t)(((kB + 16) * 16 + (nB ^ ((kB + 16) & 7))) * 16);

    auto loadStage = [&](uint32_t so) {
        cpa16u(dA0 + so, srcA0);
        cpa16u(dA1 + so, srcA1);
        cpa16u(dB0 + so, srcB0);
        cpa16u(dB1 + so, srcB1);
        srcB0 += 32 * Ln; srcB1 += 32 * Ln;
        srcA0 += 32; srcA1 += 32;
    };

    uint32_t aAddr[2][2], bAddr[4];
    #pragma unroll
    for (int mt = 0; mt < 2; mt++)
        #pragma unroll
        for (int ks = 0; ks < 2; ks++) {
            int rowp = wm * 32 + mt * 16 + (lane & 15);
            int physA = ((ks * 2) + (lane >> 4)) ^ ((rowp >> 1) & 3);
            aAddr[mt][ks] = asBase + (uint32_t)(rowp * 64 + physA * 16);
        }
    #pragma unroll
    for (int pr = 0; pr < 4; pr++) {
        int phys = (wn * 8 + pr * 2 + (lane >> 4)) ^ (lane & 7);
        bAddr[pr] = bBase + (uint32_t)((lane & 15) * 256 + phys * 16);
    }

    const int nIt = KDIM >> 5;
    loadStage(0);
    asm volatile("cp.async.commit_group;\n");
    loadStage(8192);
    asm volatile("cp.async.commit_group;\n");

    uint32_t ldSlot = 16384, sOff = 0;
    for (int it = 0; it < nIt; it++) {
        if (it + 1 < nIt) asm volatile("cp.async.wait_group 1;\n");
        else              asm volatile("cp.async.wait_group 0;\n");
        __syncthreads();
        if (it + 2 < nIt) {
            loadStage(ldSlot);
            ldSlot = (ldSlot == 16384) ? 0 : ldSlot + 8192;
        }
        asm volatile("cp.async.commit_group;\n");

        #pragma unroll
        for (int ks = 0; ks < 2; ks++) {
            uint32_t fa[2][4];
            {
                uint32_t t0, t1, t2, t3;
                ldsm4(aAddr[0][ks] + sOff, t0, t1, t2, t3);
                fa[0][0] = t0; fa[0][1] = t1; fa[0][2] = t2; fa[0][3] = t3;
                ldsm4(aAddr[1][ks] + sOff, t0, t1, t2, t3);
                fa[1][0] = t0; fa[1][1] = t1; fa[1][2] = t2; fa[1][3] = t3;
            }
            uint32_t fb[4][4];
            #pragma unroll
            for (int pr = 0; pr < 4; pr++) {
                uint32_t t0, t1, t2, t3;
                ldsm4t(bAddr[pr] + (uint32_t)(ks * 4096) + sOff, t0, t1, t2, t3);
                fb[pr][0] = t0; fb[pr][1] = t1; fb[pr][2] = t2; fb[pr][3] = t3;
            }
            #pragma unroll
            for (int mt = 0; mt < 2; mt++)
                #pragma unroll
                for (int nt = 0; nt < 8; nt++) {
                    if (ACC16) {
                        uint32_t c0 = acch[mt][nt][0], c1 = acch[mt][nt][1];
                        mma_h16(c0, c1,
                                fa[mt][0], fa[mt][1], fa[mt][2], fa[mt][3],
                                fb[nt >> 1][(nt & 1) * 2], fb[nt >> 1][(nt & 1) * 2 + 1]);
                        acch[mt][nt][0] = c0; acch[mt][nt][1] = c1;
                    } else {
                        float c0 = acc[mt][nt][0], c1 = acc[mt][nt][1];
                        float c2 = acc[mt][nt][2], c3 = acc[mt][nt][3];
                        mma_h32(c0, c1, c2, c3,
                                fa[mt][0], fa[mt][1], fa[mt][2], fa[mt][3],
                                fb[nt >> 1][(nt & 1) * 2], fb[nt >> 1][(nt & 1) * 2 + 1]);
                        acc[mt][nt][0] = c0; acc[mt][nt][1] = c1;
                        acc[mt][nt][2] = c2; acc[mt][nt][3] = c3;
                    }
                }
        }
        sOff = (sOff == 16384) ? 0 : sOff + 8192;
    }

    // epilogue
    const int row = lane >> 2, colp = (lane & 3) * 2;
    #pragma unroll
    for (int mt = 0; mt < 2; mt++) {
        #pragma unroll
        for (int h = 0; h < 2; h++) {
            int o = m0 + wm * 32 + mt * 16 + row + h * 8;
            float bb = (EPI == 5) ? 0.f : bz[o];
            float sv = (EPI == 3) ? svec[o] : 0.f;
            #pragma unroll
            for (int nt = 0; nt < 8; nt++) {
                int l = n0 + wn * 64 + nt * 8 + colp;
                ll yi = (ll)o * Ln + l;
                float r0, r1;
                if (ACC16) {
                    __half2 hv = *(__half2*)&acch[mt][nt][h];
                    r0 = __low2float(hv) + bb;
                    r1 = __high2float(hv) + bb;
                } else {
                    r0 = acc[mt][nt][h * 2 + 0] + bb;
                    r1 = acc[mt][nt][h * 2 + 1] + bb;
                }
                if (EPI == 1) { r0 = gelu_f(r0); r1 = gelu_f(r1); }
                if (EPI == 2) {
                    __half2 av = *(const __half2*)(((const hf*)aux) + yi);
                    r0 *= __low2float(av); r1 *= __high2float(av);
                }
                if (EPI == 3) {
                    float2 av = *(const float2*)(((const float*)aux) + yi);
                    r0 = av.x + sv * r0; r1 = av.y + sv * r1;
                }
                if (sizeof(OutT) == 2) {
                    __half2 pv = __floats2half2_rn(r0, r1);
                    *(__half2*)((hf*)Yz + yi) = pv;
                } else {
                    float2 fv; fv.x = r0; fv.y = r1;
                    *(float2*)((float*)Yz + yi) = fv;
                }
            }
        }
    }
}

// ---------------- generic GEMM kernel wrapper --------------------------------
template<int EPI, bool ACC16, typename OutT>
__global__ void __launch_bounds__(256, 2)
gemm_t(const hf* __restrict__ W, const float* __restrict__ bias,
       const hf* __restrict__ X, OutT* __restrict__ Y,
       int KDIM, int zB,
       ll wStrideI, int bStrideI,
       ll xStrideB, ll xStrideI,
       ll yStrideB, ll yStrideI,
       const void* __restrict__ aux, ll aStrideB, ll aStrideI,
       const float* __restrict__ svec)
{
    __shared__ __align__(16) hf As[3][128][32];
    __shared__ __align__(16) hf Bs[3][4096];
    const int z = blockIdx.z;
    const int b = z % zB, br = z / zB;
    const hf*  Wz = W + (ll)br * wStrideI;
    const float* bz = bias + (ll)br * bStrideI;
    const hf*  Xz = X + (ll)b * xStrideB + (ll)br * xStrideI;
    OutT* Yz = Y + (ll)b * yStrideB + (ll)br * yStrideI;
    const void* auxp = nullptr;
    if (EPI == 2) auxp = ((const hf*)aux) + (ll)b * aStrideB + (ll)br * aStrideI;
    if (EPI == 3) auxp = ((const float*)aux) + (ll)b * aStrideB + (ll)br * aStrideI;
    gemm_core<EPI, ACC16, OutT>(As, Bs, Wz, bz, Xz, Yz, KDIM, KDIM,
                                blockIdx.y * 128, blockIdx.x * 128, auxp, svec);
}

// ---------------- split-K partial GEMM ---------------------------------------
__global__ void __launch_bounds__(256, 2)
gpart_k(const hf* __restrict__ W, int wLD, ll wChunk,
        const hf* __restrict__ X, ll xStrideB, ll xChunk,
        float* __restrict__ parts, int KDIM, int nCh)
{
    __shared__ __align__(16) hf As[3][128][32];
    __shared__ __align__(16) hf Bs[3][4096];
    int z = blockIdx.z;
    int b = z % Bn, ch = z / Bn;
    const hf* Wz = W + (ll)ch * wChunk;
    const hf* Xz = X + (ll)b * xStrideB + (ll)ch * xChunk;
    float* Yz = parts + (ll)ch * BCL + (ll)b * Cn * Ln;
    gemm_core<5, false, float>(As, Bs, Wz, nullptr, Xz, Yz, KDIM, wLD,
                               blockIdx.y * 128, blockIdx.x * 128, nullptr, nullptr);
}

// ---------------- split-K epilogue: out = aux + svec*(sum(parts) + bias) ------
template<int NC>
__global__ void __launch_bounds__(256)
ey_k(const float* __restrict__ parts, const float* __restrict__ auxf,
     const float* __restrict__ svec, const float* __restrict__ bias,
     float* __restrict__ out)
{
    int i = blockIdx.x * 256 + threadIdx.x;
    int c = (i >> 9) & 255;
    float s = 0.f;
    #pragma unroll
    for (int q = 0; q < NC; q++) s += parts[(ll)q * BCL + i];
    out[i] = auxf[i] + svec[c] * (s + bias[c]);
}

// ---------------- merged G1+G2 kernel -----------------------------------------
__global__ void __launch_bounds__(256, 2)
g12_k(const hf* __restrict__ wa, const float* __restrict__ ba,
      const hf* __restrict__ wv, const float* __restrict__ bv,
      const hf* __restrict__ xb, hf* __restrict__ ag, hf* __restrict__ vvp)
{
    __shared__ __align__(16) hf As[3][128][32];
    __shared__ __align__(16) hf Bs[3][4096];
    int t = blockIdx.y;
    int b = blockIdx.z;
    const ll SB = (ll)NPn * Cn * Ln;
    const hf* Xz = xb + (ll)b * Cn * Ln;
    if (t < 12) {
        gemm_core<1, true, hf>(As, Bs, wa, ba, Xz, ag + (ll)b * SB, Cn, Cn,
                               t * 128, blockIdx.x * 128, nullptr, nullptr);
    } else {
        gemm_core<0, true, hf>(As, Bs, wv, bv, Xz, vvp + (ll)b * SB, Cn, Cn,
                               (t - 12) * 128, blockIdx.x * 128, nullptr, nullptr);
    }
}

// ---------------- fused off+ml+G3 mega-GEMM -----------------------------------
__global__ void __launch_bounds__(256, 2)
offml_k(const hf* __restrict__ woff, const hf* __restrict__ wm,
        const float* __restrict__ boff, const float* __restrict__ bm,
        const hf* __restrict__ wvd, const float* __restrict__ bvd,
        const hf* __restrict__ ag, hf* __restrict__ offp, hf* __restrict__ mlp,
        hf* __restrict__ vp)
{
    __shared__ __align__(16) hf As[3][128][32];
    __shared__ __align__(16) hf Bs[3][4096];
    const int bnd[7]  = {0, 14, 32, 54, 80, 110, 144};
    const int preK[6] = {0, 7, 16, 27, 40, 55};
    int t = blockIdx.y;
    int b = blockIdx.z;
    const ll SI = (ll)Cn * Ln;
    if (t >= 288) {
        int t2 = t - 288;
        int br = t2 >> 1, mt = t2 & 1;
        const hf* Xz = ag + ((ll)b * NPn + br) * SI;
        gemm_core<0, true, hf>(As, Bs, wvd + (ll)br * Cn * Cn, bvd + br * Cn,
                               Xz, vp + ((ll)b * NPn + br) * SI, Cn, Cn,
                               mt * 128, blockIdx.x * 128, nullptr, nullptr);
        return;
    }
    int kind = (t >= 144) ? 1 : 0;
    int tt = t - kind * 144;
    int br = 0;
    #pragma unroll
    for (int j = 1; j < 6; j++) if (tt >= bnd[j]) br = j;
    int mloc = (tt - bnd[br]) * 128;
    int K = 7 + 2 * br;
    const hf*    W  = (kind ? wm : woff) + (ll)br * KMAXn * Cn * Cn + (ll)mloc * Cn;
    const float* bz = (kind ? bm : boff) + br * KMAXn * Cn + mloc;
    const hf*    Xz = ag + ((ll)b * NPn + br) * SI;
    hf* Y = (kind ? mlp : offp) + (ll)preK[br] * BCL
            + (ll)b * Cn * K * Ln + (ll)mloc * Ln;
    gemm_core<0, true, hf>(As, Bs, W, bz, Xz, Y, Cn, Cn, 0, blockIdx.x * 128,
                           nullptr, nullptr);
}

// ---------------- DCN (fast exp, single fused K-loop) --------------------------
template<int K>
__device__ __forceinline__ void dcn_body(
    const hf* __restrict__ off_all, const hf* __restrict__ ml_all,
    const hf* __restrict__ v_all, hf* __restrict__ dcn,
    int branch, ll regionBase)
{
    ll idx = (ll)blockIdx.x * 256 + threadIdx.x;
    int l = (int)(idx & (Ln - 1));
    int c = (int)((idx >> 9) & (Cn - 1));
    int b = (int)(idx >> 17);
    ll rowBase = regionBase + ((ll)b * Cn * K + (ll)c * K) * Ln + l;
    const hf* op = off_all + rowBase;
    const hf* mp = ml_all + rowBase;
    const hf* vp = v_all + ((ll)b * NPn + branch) * ((ll)Cn * Ln) + (ll)c * Ln;

    // softmax without max-subtraction: |ml| is small by construction (weights
    // scale 0.05), exp cannot overflow fp32; shift-invariance => same result.
    float s = 0.f, acc = 0.f;
    #pragma unroll
    for (int k = 0; k < K; k++) {
        float e = __expf(__half2float(mp[(ll)k * Ln]));
        s += e;
        float p = (float)l + ((float)k - (float)(K - 1) * 0.5f)
                + __half2float(op[(ll)k * Ln]);
        float p0 = floorf(p);
        float w = p - p0;
        int i0 = (int)p0;
        float ga = (i0 >= 0 && i0 < Ln) ? __half2float(vp[i0]) : 0.f;
        float gb = (i0 + 1 >= 0 && i0 + 1 < Ln) ? __half2float(vp[i0 + 1]) : 0.f;
        acc = fmaf(e, fmaf(w, gb - ga, ga), acc);
    }
    dcn[((ll)b * NPn + branch) * ((ll)Cn * Ln) + (ll)c * Ln + l]
        = __float2half(__fdividef(acc, s));
}

__global__ void __launch_bounds__(256)
dcnall_k(const hf* __restrict__ offp, const hf* __restrict__ mlp,
         const hf* __restrict__ vp, hf* __restrict__ dcnp)
{
    switch (blockIdx.y) {
        case 0: dcn_body<7 >(offp, mlp, vp, dcnp, 0, (ll)0 * BCL);  break;
        case 1: dcn_body<9 >(offp, mlp, vp, dcnp, 1, (ll)7 * BCL);  break;
        case 2: dcn_body<11>(offp, mlp, vp, dcnp, 2, (ll)16 * BCL); break;
        case 3: dcn_body<13>(offp, mlp, vp, dcnp, 3, (ll)27 * BCL); break;
        case 4: dcn_body<15>(offp, mlp, vp, dcnp, 4, (ll)40 * BCL); break;
        default: dcn_body<17>(offp, mlp, vp, dcnp, 5, (ll)55 * BCL); break;
    }
}

// ---------------- LayerNorm over C ------------------------------------------
__global__ void __launch_bounds__(256)
ln_k(const float* __restrict__ y, const float* __restrict__ g,
     const float* __restrict__ be, hf* __restrict__ tn)
{
    int l = blockIdx.x * 256 + threadIdx.x;
    int b = blockIdx.y;
    const float* yp = y + (ll)b * Cn * Ln + l;
    float s = 0.f, s2 = 0.f;
    #pragma unroll 8
    for (int c = 0; c < Cn; c++) {
        float v = yp[(ll)c * Ln];
        s += v; s2 += v * v;
    }
    float mu = s * (1.0f / Cn);
    float var = s2 * (1.0f / Cn) - mu * mu;
    float rstd = rsqrtf(var + 1e-6f);
    hf* tp = tn + (ll)b * Cn * Ln + l;
    #pragma unroll 8
    for (int c = 0; c < Cn; c++) {
        float v = yp[(ll)c * Ln];
        tp[(ll)c * Ln] = __float2half((v - mu) * rstd * g[c] + be[c]);
    }
}

// ----------------------------------------------------------------------------
extern "C" void kernel_launch(void* const* d_in, const int* in_sizes, int n_in,
                              void* d_out, int out_size)
{
    const float* x    = (const float*)d_in[0];
    const float* Wa   = (const float*)d_in[1];
    const float* ba   = (const float*)d_in[2];
    const float* Wvd  = (const float*)d_in[3];
    const float* bvd  = (const float*)d_in[4];
    const float* Woff = (const float*)d_in[5];
    const float* boff = (const float*)d_in[6];
    const float* Wm   = (const float*)d_in[7];
    const float* bm   = (const float*)d_in[8];
    const float* Wod  = (const float*)d_in[9];
    const float* bod  = (const float*)d_in[10];
    const float* Wv   = (const float*)d_in[11];
    const float* bv   = (const float*)d_in[12];
    const float* Wp   = (const float*)d_in[13];
    const float* bp   = (const float*)d_in[14];
    const float* ls   = (const float*)d_in[15];
    const float* g2   = (const float*)d_in[16];
    const float* lng  = (const float*)d_in[17];
    const float* lnb  = (const float*)d_in[18];
    const float* W1   = (const float*)d_in[19];
    const float* b1   = (const float*)d_in[20];
    const float* W2   = (const float*)d_in[21];
    const float* b2   = (const float*)d_in[22];
    float* out = (float*)d_out;

    hf *ag, *vvp, *vp, *dcnp, *prodp, *offp, *mlp, *tnp, *hp, *xb;
    hf *wa, *wvd, *wod, *wv, *wps, *woff, *wm, *w1, *w2;
    float *yp, *bps, *parts;
    cudaGetSymbolAddress((void**)&ag,    g_ag);
    cudaGetSymbolAddress((void**)&vvp,   g_vv);
    cudaGetSymbolAddress((void**)&vp,    g_v);
    cudaGetSymbolAddress((void**)&dcnp,  g_dcn);
    cudaGetSymbolAddress((void**)&prodp, g_prod);
    cudaGetSymbolAddress((void**)&offp,  g_off);
    cudaGetSymbolAddress((void**)&mlp,   g_ml);
    cudaGetSymbolAddress((void**)&yp,    g_y);
    cudaGetSymbolAddress((void**)&tnp,   g_tn);
    cudaGetSymbolAddress((void**)&hp,    g_h);
    cudaGetSymbolAddress((void**)&bps,   g_bps);
    cudaGetSymbolAddress((void**)&parts, g_part);
    cudaGetSymbolAddress((void**)&wa,    g_wa);
    cudaGetSymbolAddress((void**)&wvd,   g_wvd);
    cudaGetSymbolAddress((void**)&wod,   g_wod);
    cudaGetSymbolAddress((void**)&wv,    g_wv);
    cudaGetSymbolAddress((void**)&wps,   g_wps);
    cudaGetSymbolAddress((void**)&woff,  g_woff);
    cudaGetSymbolAddress((void**)&wm,    g_wm);
    cudaGetSymbolAddress((void**)&w1,    g_w1);
    cudaGetSymbolAddress((void**)&w2,    g_w2);
    cudaGetSymbolAddress((void**)&xb,    g_xb);

    // fused conversions (single launch) + Wp permute + bias sum
    CvtArgs ca;
    const float* srcs[9] = {x, Wa, Wvd, Wod, Wv, Woff, Wm, W1, W2};
    hf* dsts[9] = {xb, wa, wvd, wod, wv, woff, wm, w1, w2};
    int cnts[9] = {Bn*Cn*Ln, NPn*Cn*Cn, NPn*Cn*Cn, NPn*Cn*Cn, NPn*Cn*Cn,
                   NPn*KMAXn*Cn*Cn, NPn*KMAXn*Cn*Cn, HIDn*Cn, Cn*HIDn};
    ca.cum[0] = 0;
    for (int i = 0; i < 9; i++) {
        ca.src[i] = srcs[i]; ca.dst[i] = dsts[i];
        ca.cum[i + 1] = ca.cum[i] + cnts[i];
    }
    cvtall_k<<<8192, 256>>>(ca);
    wps_k<<<1536, 256>>>(Wp, wps);
    bpsum_k<<<1, 256>>>(bp, bps);

    const ll SB = (ll)NPn * Cn * Ln;
    const ll SI = (ll)Cn * Ln;

    // G1+G2 merged: ag = gelu(Wa@x + ba); vv = Wv@x + bv   (f16 accum)
    g12_k<<<dim3(4, 24, Bn), 256>>>(wa, ba, wv, bv, xb, ag, vvp);
    // G4+G5+G3 mega-grid: off/ml projections + v = Wvd@ag   (f16 accum)
    offml_k<<<dim3(4, 300, Bn), 256>>>(woff, wm, boff, bm, wvd, bvd,
                                       ag, offp, mlp, vp);
    // G6: DCN sampling (fast exp, fused loop)
    dcnall_k<<<dim3((Bn * Cn * Ln) / 256, NPn), 256>>>(offp, mlp, vp, dcnp);
    // G7: prod = (Wod[i]@dcn_i + bod[i]) * vv_i      (f16 accum)
    gemm_t<2, true, hf><<<dim3(4, Cn / 128, NPn * Bn), 256>>>(
        wod, bod, dcnp, prodp, Cn, Bn, (ll)Cn * Cn, Cn, SB, SI, SB, SI,
        vvp, SB, SI, nullptr);
    // G8 split-K: 4 chunks of K=384 over stacked Wp -> partials, then epilogue
    gpart_k<<<dim3(4, 2, 4 * Bn), 256>>>(
        wps, NPn * Cn, (ll)384, prodp, SB, (ll)384 * Ln, parts, 384, 4);
    ey_k<4><<<(int)(BCL / 256), 256>>>(parts, x, ls, bps, yp);
    // G9: LayerNorm
    ln_k<<<dim3(Ln / 256, Bn), 256>>>(yp, lng, lnb, tnp);
    // G10: h = gelu(W1@tn + b1)                      (f16 accum)
    gemm_t<1, true, hf><<<dim3(4, HIDn / 128, Bn), 256>>>(
        w1, b1, tnp, hp, Cn, Bn, 0, 0, SI, 0, (ll)HIDn * Ln, 0,
        nullptr, 0, 0, nullptr);
    // G11 split-K: 4 chunks of K=256 over HID -> partials, then epilogue
    gpart_k<<<dim3(4, 2, 4 * Bn), 256>>>(
        w2, HIDn, (ll)256, hp, (ll)HIDn * Ln, (ll)256 * Ln, parts, 256, 4);
    ey_k<4><<<(int)(BCL / 256), 256>>>(parts, yp, g2, b2, out);
}